// round 13
// baseline (speedup 1.0000x reference)
#include <cuda_runtime.h>
#include <cuda_bf16.h>
#include <cuda_fp16.h>
#include <math.h>

#define B_  2
#define S_  2048
#define D_  1024
#define H_  16
#define DK  64
#define BH_ (B_*H_)
#define MS_ (B_*S_)          // 4096 rows

// ---------------- scratch (static device arrays; no cudaMalloc) ----------------
__device__ float g_v[(size_t)MS_*D_];
__device__ __half g_sh[(size_t)BH_*S_*S_];      // u = exp(s/8), fp16 (256 MB)
__device__ float g_sumv[BH_*DK];
__device__ __half g_xh[(size_t)MS_*D_];          // x fp16
__device__ __half g_ah[(size_t)MS_*D_];          // attn fp16
__device__ __half g_wt[4][(size_t)D_*D_];        // W^T fp16 ([n][k])
__device__ __half g_qh[(size_t)MS_*D_];          // roped q fp16
__device__ __half g_kh[(size_t)MS_*D_];          // roped k fp16
__device__ __half g_vth[(size_t)BH_*DK*S_];      // V^T fp16 [b*h][dk][s]

// ================= helpers =================
__device__ __forceinline__ unsigned smem_u32(const void* p) {
    unsigned a;
    asm("{ .reg .u64 t; cvta.to.shared.u64 t, %1; cvt.u32.u64 %0, t; }" : "=r"(a) : "l"(p));
    return a;
}
__device__ __forceinline__ void cp16(unsigned saddr, const void* gaddr) {
    asm volatile("cp.async.cg.shared.global [%0], [%1], 16;" :: "r"(saddr), "l"(gaddr));
}
__device__ __forceinline__ void cp_commit() { asm volatile("cp.async.commit_group;"); }
template <int N>
__device__ __forceinline__ void cp_wait() { asm volatile("cp.async.wait_group %0;" :: "n"(N)); }

__device__ __forceinline__ void mma16816(float* c, const unsigned* a, unsigned b0, unsigned b1) {
    asm volatile("mma.sync.aligned.m16n8k16.row.col.f32.f16.f16.f32 "
                 "{%0,%1,%2,%3}, {%4,%5,%6,%7}, {%8,%9}, {%0,%1,%2,%3};"
                 : "+f"(c[0]), "+f"(c[1]), "+f"(c[2]), "+f"(c[3])
                 : "r"(a[0]), "r"(a[1]), "r"(a[2]), "r"(a[3]), "r"(b0), "r"(b1));
}

// ================= convert / transform kernels =================
__global__ void convX(const float* __restrict__ X, __half* __restrict__ out) {
    int i = blockIdx.x * 256 + threadIdx.x;
    out[i] = __float2half(X[i]);
}

// batched: W[z][k][n] -> WT fp16 [z][n][k]
__global__ void convWT4(const float* __restrict__ W0, const float* __restrict__ W1,
                        const float* __restrict__ W2, const float* __restrict__ W3,
                        __half* __restrict__ wt) {
    __shared__ float t[32][33];
    const float* Ws[4] = {W0, W1, W2, W3};
    const float* W = Ws[blockIdx.z];
    __half* dst = wt + (size_t)blockIdx.z * D_ * D_;
    int bx = blockIdx.x * 32, by = blockIdx.y * 32;
    int tx = threadIdx.x & 31, ty = threadIdx.x >> 5;
#pragma unroll
    for (int i = 0; i < 32; i += 8)
        t[ty + i][tx] = W[(size_t)(by + ty + i) * 1024 + bx + tx];
    __syncthreads();
#pragma unroll
    for (int i = 0; i < 32; i += 8)
        dst[(size_t)(bx + ty + i) * 1024 + by + tx] = __float2half(t[tx][ty + i]);
}

// V [b][s][h][dk] fp32 -> V^T [b*h][dk][s] fp16
__global__ void vtrans(const float* __restrict__ v, __half* __restrict__ vth) {
    __shared__ float t[32][33];
    int s0 = blockIdx.x * 32, d0 = blockIdx.y * 32;
    int bh = blockIdx.z, b = bh >> 4, h = bh & 15;
    int tx = threadIdx.x & 31, ty = threadIdx.x >> 5;
#pragma unroll
    for (int i = 0; i < 32; i += 8)
        t[ty + i][tx] = v[((size_t)(b * S_ + s0 + ty + i)) * D_ + h * DK + d0 + tx];
    __syncthreads();
#pragma unroll
    for (int i = 0; i < 32; i += 8)
        vth[((size_t)bh * DK + d0 + ty + i) * S_ + s0 + tx] = __float2half(t[tx][ty + i]);
}

// sumv[bh][d] = sum_s v[b][s][h][d]  (exact fp32)
__global__ void sumv_kernel(const float* __restrict__ v, float* __restrict__ sumv) {
    int bh = blockIdx.x, b = bh >> 4, h = bh & 15;
    int d = threadIdx.x & 63, sc = threadIdx.x >> 6;
    float s = 0.f;
    for (int i = 0; i < 512; i++)
        s += v[((size_t)(b * S_ + sc * 512 + i)) * D_ + h * DK + d];
    __shared__ float red[256];
    red[threadIdx.x] = s;
    __syncthreads();
    if (sc == 0) sumv[bh * DK + d] = red[d] + red[64 + d] + red[128 + d] + red[192 + d];
}

// ================= 1-term fp16 GEMM, K-chunk 64 =================
#define SA2    72                    // smem row stride in halves (144 B), conflict-free
#define TILE2  (128 * SA2 * 2)       // 18432 B per tile
#define BUF2   (2 * TILE2)           // 36864 B (A + B tiles)
#define G2SMEM (2 * BUF2)            // 73728 B double buffered

// shared mainloop: 16 chunks of K=64
#define GEMM_MAIN64(ACCUM)                                                          \
    {                                                                               \
        _Pragma("unroll")                                                           \
        for (int t = 0; t < 2; t++)                                                 \
            _Pragma("unroll")                                                       \
            for (int u = 0; u < 4; u++) {                                           \
                int idx = tid * 4 + u;                 /* 0..1023 */                \
                int row = idx >> 3, seg = idx & 7;                                  \
                cp16(sb + t * TILE2 + row * 144 + seg * 16,                         \
                     srcs[t] + (size_t)(r0s[t] + row) * 1024 + seg * 8);            \
            }                                                                       \
        cp_commit();                                                                \
    }                                                                               \
    for (int ch = 0; ch < 16; ch++) {                                               \
        const int buf = ch & 1;                                                     \
        if (ch < 15) {                                                              \
            const int k0 = (ch + 1) * 64, nbuf = (ch + 1) & 1;                      \
            _Pragma("unroll")                                                       \
            for (int t = 0; t < 2; t++)                                             \
                _Pragma("unroll")                                                   \
                for (int u = 0; u < 4; u++) {                                       \
                    int idx = tid * 4 + u;                                          \
                    int row = idx >> 3, seg = idx & 7;                              \
                    cp16(sb + nbuf * BUF2 + t * TILE2 + row * 144 + seg * 16,       \
                         srcs[t] + (size_t)(r0s[t] + row) * 1024 + k0 + seg * 8);   \
                }                                                                   \
            cp_commit();                                                            \
            cp_wait<1>();                                                           \
        } else {                                                                    \
            cp_wait<0>();                                                           \
        }                                                                           \
        __syncthreads();                                                            \
        const __half* Ah = (const __half*)(smc + buf * BUF2);                       \
        const __half* Bh = Ah + 128 * SA2;                                          \
        _Pragma("unroll")                                                           \
        for (int kk = 0; kk < 64; kk += 16) {                                       \
            unsigned af[2][4];                                                      \
            _Pragma("unroll")                                                       \
            for (int mt = 0; mt < 2; mt++) {                                        \
                int r = wm * 32 + mt * 16 + grp;                                    \
                af[mt][0] = *(const unsigned*)&Ah[r * SA2 + kk + qid * 2];          \
                af[mt][1] = *(const unsigned*)&Ah[(r + 8) * SA2 + kk + qid * 2];    \
                af[mt][2] = *(const unsigned*)&Ah[r * SA2 + kk + 8 + qid * 2];      \
                af[mt][3] = *(const unsigned*)&Ah[(r + 8) * SA2 + kk + 8 + qid * 2];\
            }                                                                       \
            _Pragma("unroll")                                                       \
            for (int nt = 0; nt < 8; nt++) {                                        \
                int c = wn * 64 + nt * 8 + grp;                                     \
                unsigned b0 = *(const unsigned*)&Bh[c * SA2 + kk + qid * 2];        \
                unsigned b1 = *(const unsigned*)&Bh[c * SA2 + kk + 8 + qid * 2];    \
                _Pragma("unroll")                                                   \
                for (int mt = 0; mt < 2; mt++)                                      \
                    mma16816(ACCUM[mt][nt], af[mt], b0, b1);                        \
            }                                                                       \
        }                                                                           \
        __syncthreads();                                                            \
    }

// plain: C fp32 = A fp16 @ W^T fp16
__global__ __launch_bounds__(256, 2) void gemm_f16(const __half* __restrict__ Ah_,
                                                   const __half* __restrict__ Bh_,
                                                   float* __restrict__ C) {
    extern __shared__ char smc[];
    const int tid = threadIdx.x, lane = tid & 31, wid = tid >> 5;
    const int wm = wid & 3, wn = wid >> 2;
    const int grp = lane >> 2, qid = lane & 3;
    const int m0 = blockIdx.y * 128, n0 = blockIdx.x * 128;
    const unsigned sb = smem_u32(smc);

    const __half* srcs[2] = {Ah_, Bh_};
    const int r0s[2] = {m0, n0};

    float acc[2][8][4];
#pragma unroll
    for (int mt = 0; mt < 2; mt++)
#pragma unroll
        for (int nt = 0; nt < 8; nt++)
#pragma unroll
            for (int e = 0; e < 4; e++) acc[mt][nt][e] = 0.f;

    GEMM_MAIN64(acc)

#pragma unroll
    for (int mt = 0; mt < 2; mt++) {
        int r = m0 + wm * 32 + mt * 16 + grp;
#pragma unroll
        for (int nt = 0; nt < 8; nt++) {
            int c = n0 + wn * 64 + nt * 8 + qid * 2;
            *(float2*)&C[(size_t)r * 1024 + c]       = make_float2(acc[mt][nt][0], acc[mt][nt][1]);
            *(float2*)&C[(size_t)(r + 8) * 1024 + c] = make_float2(acc[mt][nt][2], acc[mt][nt][3]);
        }
    }
}

// z-batched (Wq, Wk) GEMM with fused RoPE epilogue -> fp16
__global__ __launch_bounds__(256, 2) void gemm_rope2(const __half* __restrict__ Ah_,
                                                     const __half* __restrict__ wt,
                                                     const float* __restrict__ fc,
                                                     const float* __restrict__ fs,
                                                     __half* __restrict__ qdst,
                                                     __half* __restrict__ kdst) {
    extern __shared__ char smc[];
    const int tid = threadIdx.x, lane = tid & 31, wid = tid >> 5;
    const int wm = wid & 3, wn = wid >> 2;
    const int grp = lane >> 2, qid = lane & 3;
    const int m0 = blockIdx.y * 128, n0 = blockIdx.x * 128;
    const unsigned sb = smem_u32(smc);

    const __half* Bh_ = wt + (size_t)blockIdx.z * D_ * D_;
    __half* dst = blockIdx.z ? kdst : qdst;

    const __half* srcs[2] = {Ah_, Bh_};
    const int r0s[2] = {m0, n0};

    float acc[2][8][4];
#pragma unroll
    for (int mt = 0; mt < 2; mt++)
#pragma unroll
        for (int nt = 0; nt < 8; nt++)
#pragma unroll
            for (int e = 0; e < 4; e++) acc[mt][nt][e] = 0.f;

    GEMM_MAIN64(acc)

    // fused RoPE epilogue -> fp16 (pairs (c, c+1) are (re, im) within head)
#pragma unroll
    for (int mt = 0; mt < 2; mt++) {
        int r = m0 + wm * 32 + mt * 16 + grp;
        int s = r & (S_ - 1);
#pragma unroll
        for (int nt = 0; nt < 8; nt++) {
            int c = n0 + wn * 64 + nt * 8 + qid * 2;
            int ii = (c & 63) >> 1;
            float c0 = fc[s * 32 + ii],       s0 = fs[s * 32 + ii];
            float c1 = fc[(s + 8) * 32 + ii], s1 = fs[(s + 8) * 32 + ii];
            float re0 = acc[mt][nt][0], im0 = acc[mt][nt][1];
            float re1 = acc[mt][nt][2], im1 = acc[mt][nt][3];
            __half2 p0, p1;
            p0.x = __float2half(re0 * c0 - im0 * s0);
            p0.y = __float2half(re0 * s0 + im0 * c0);
            p1.x = __float2half(re1 * c1 - im1 * s1);
            p1.y = __float2half(re1 * s1 + im1 * c1);
            *(__half2*)&dst[(size_t)r * 1024 + c]       = p0;
            *(__half2*)&dst[(size_t)(r + 8) * 1024 + c] = p1;
        }
    }
}

// ================= fused attention: pass1 + pass2 =================
#define P1S   72
#define P1ROW (P1S * 2)
#define P1T   (128 * P1ROW)   // 18432
#define P2S   136
#define P2ROW (P2S * 2)
#define P2TT  (128 * P2ROW)   // 34816
#define P2VT  (64 * P2ROW)    // 17408
#define FA_ZBUF (3 * P1T)
#define FA_SZ   (3 * P1T + 1024)
#define FASMEM  (3 * P1T + 2048)    // 57344

__global__ __launch_bounds__(256, 2) void attn_fused(const __half* __restrict__ qh,
                                                     const __half* __restrict__ kh,
                                                     const __half* __restrict__ vth,
                                                     const float* __restrict__ sumv,
                                                     __half* __restrict__ aout) {
    extern __shared__ char smc[];
    const unsigned sb = smem_u32(smc);
    const int tid = threadIdx.x, lane = tid & 31, wid = tid >> 5;
    const int wm = wid & 3, wn = wid >> 2;
    const int grp = lane >> 2, qid = lane & 3;
    const int bh = blockIdx.y, b = bh >> 4, h = bh & 15;
    const int q0 = blockIdx.x * 128;
    const int ty = tid >> 4, tx = tid & 15;
    float* zbuf = (float*)(smc + FA_ZBUF);
    float* sz   = (float*)(smc + FA_SZ);

    // ======== phase A: u = exp(QK^T/8) -> fp16 gmem, z = sum u -> smem ========
    {
#pragma unroll
        for (int u = 0; u < 4; u++) {
            int idx = tid * 4 + u;
            int row = idx >> 3, ch = idx & 7;
            cp16(sb + row * P1ROW + ch * 16,
                 qh + ((size_t)(b * S_ + q0 + row)) * D_ + h * DK + ch * 8);
        }
#pragma unroll
        for (int u = 0; u < 4; u++) {
            int idx = tid * 4 + u;
            int row = idx >> 3, ch = idx & 7;
            cp16(sb + P1T + row * P1ROW + ch * 16,
                 kh + ((size_t)(b * S_ + row)) * D_ + h * DK + ch * 8);
        }
        cp_commit();
    }
    cp_wait<0>();
    __syncthreads();

    unsigned qf[2][4][4];
    {
        const __half* Qh = (const __half*)smc;
#pragma unroll
        for (int mt = 0; mt < 2; mt++) {
            int r = wm * 32 + mt * 16 + grp;
#pragma unroll
            for (int kk = 0; kk < 4; kk++) {
                int c0 = kk * 16 + qid * 2;
                qf[mt][kk][0] = *(const unsigned*)&Qh[r * P1S + c0];
                qf[mt][kk][1] = *(const unsigned*)&Qh[(r + 8) * P1S + c0];
                qf[mt][kk][2] = *(const unsigned*)&Qh[r * P1S + c0 + 8];
                qf[mt][kk][3] = *(const unsigned*)&Qh[(r + 8) * P1S + c0 + 8];
            }
        }
    }

    float zacc[2][2] = {{0.f, 0.f}, {0.f, 0.f}};

    for (int kt = 0; kt < 16; kt++) {
        const int buf = kt & 1;
        if (kt < 15) {
            const int nbuf = (kt + 1) & 1;
#pragma unroll
            for (int u = 0; u < 4; u++) {
                int idx = tid * 4 + u;
                int row = idx >> 3, ch = idx & 7;
                cp16(sb + (1 + nbuf) * P1T + row * P1ROW + ch * 16,
                     kh + ((size_t)(b * S_ + (kt + 1) * 128 + row)) * D_ + h * DK + ch * 8);
            }
            cp_commit();
            cp_wait<1>();
        } else {
            cp_wait<0>();
        }
        __syncthreads();

        const __half* Kh = (const __half*)(smc + (1 + buf) * P1T);

        float acc[2][8][4];
#pragma unroll
        for (int mt = 0; mt < 2; mt++)
#pragma unroll
            for (int nt = 0; nt < 8; nt++)
#pragma unroll
                for (int e = 0; e < 4; e++) acc[mt][nt][e] = 0.f;

#pragma unroll
        for (int kk = 0; kk < 4; kk++) {
#pragma unroll
            for (int nt = 0; nt < 8; nt++) {
                int c = wn * 64 + nt * 8 + grp;
                int c0 = kk * 16 + qid * 2;
                unsigned b0 = *(const unsigned*)&Kh[c * P1S + c0];
                unsigned b1 = *(const unsigned*)&Kh[c * P1S + c0 + 8];
#pragma unroll
                for (int mt = 0; mt < 2; mt++)
                    mma16816(acc[mt][nt], qf[mt][kk], b0, b1);
            }
        }

        // epilogue: u = exp(s/8) -> fp16 gmem, z += u
#pragma unroll
        for (int mt = 0; mt < 2; mt++) {
            int r = q0 + wm * 32 + mt * 16 + grp;
#pragma unroll
            for (int nt = 0; nt < 8; nt++) {
                int c = kt * 128 + wn * 64 + nt * 8 + qid * 2;
                float u0 = __expf(acc[mt][nt][0] * 0.125f);
                float u1 = __expf(acc[mt][nt][1] * 0.125f);
                float u2 = __expf(acc[mt][nt][2] * 0.125f);
                float u3 = __expf(acc[mt][nt][3] * 0.125f);
                *(__half2*)&g_sh[((size_t)bh * S_ + r) * S_ + c]     = __floats2half2_rn(u0, u1);
                *(__half2*)&g_sh[((size_t)bh * S_ + r + 8) * S_ + c] = __floats2half2_rn(u2, u3);
                zacc[mt][0] += u0 + u1;
                zacc[mt][1] += u2 + u3;
            }
        }
        __syncthreads();
    }

#pragma unroll
    for (int mt = 0; mt < 2; mt++)
#pragma unroll
        for (int hf = 0; hf < 2; hf++) {
            float z = zacc[mt][hf];
            z += __shfl_xor_sync(0xffffffffu, z, 1);
            z += __shfl_xor_sync(0xffffffffu, z, 2);
            if (qid == 0) zbuf[wn * 128 + wm * 32 + mt * 16 + hf * 8 + grp] = z;
        }
    __syncthreads();
    if (tid < 128) sz[tid] = zbuf[tid] + zbuf[128 + tid];
    __syncthreads();

    // ======== phase B: p = u/z; t = p + p^2/2; out = (sumv + tV)/(2048+sum t) ====
    __half* Th = (__half*)smc;
    const __half* Vh = (const __half*)(smc + P2TT);
    float* tsums = (float*)(smc + P2TT + P2VT);

    float iz[8], tsum[8];
#pragma unroll
    for (int i = 0; i < 8; i++) {
        iz[i] = 1.0f / sz[ty * 8 + i];
        tsum[i] = 0.f;
    }

    float acc2[2][4][4];
#pragma unroll
    for (int mt = 0; mt < 2; mt++)
#pragma unroll
        for (int nt = 0; nt < 4; nt++)
#pragma unroll
            for (int e = 0; e < 4; e++) acc2[mt][nt][e] = 0.f;

    for (int kt = 0; kt < 16; kt++) {
        const int k0 = kt * 128;
        {
#pragma unroll
            for (int u = 0; u < 4; u++) {
                int idx = tid * 4 + u;                 // 0..1023
                int row = idx >> 4, ch = idx & 15;
                cp16(sb + P2TT + row * P2ROW + ch * 16,
                     vth + ((size_t)bh * DK + row) * S_ + k0 + ch * 8);
            }
            cp_commit();
        }
        // t tile from fp16 u values — no MUFU here
#pragma unroll
        for (int i = 0; i < 8; i++) {
            int r = ty * 8 + i;
#pragma unroll
            for (int hf = 0; hf < 2; hf++) {
                int c = hf * 64 + tx * 4;
                struct alignas(8) H4 { __half2 a, b; };
                H4 s4 = *(const H4*)&g_sh[((size_t)bh * S_ + q0 + r) * S_ + k0 + c];
                float2 f01 = __half22float2(s4.a);
                float2 f23 = __half22float2(s4.b);
                float p0 = f01.x * iz[i];
                float p1 = f01.y * iz[i];
                float p2 = f23.x * iz[i];
                float p3 = f23.y * iz[i];
                float t0 = fmaf(0.5f * p0, p0, p0);   // expm1(p), p <= ~0.006
                float t1 = fmaf(0.5f * p1, p1, p1);
                float t2 = fmaf(0.5f * p2, p2, p2);
                float t3 = fmaf(0.5f * p3, p3, p3);
                tsum[i] += (t0 + t1) + (t2 + t3);
                *(__half2*)&Th[r * P2S + c]     = __floats2half2_rn(t0, t1);
                *(__half2*)&Th[r * P2S + c + 2] = __floats2half2_rn(t2, t3);
            }
        }
        cp_wait<0>();
        __syncthreads();

#pragma unroll
        for (int kk = 0; kk < 8; kk++) {
            unsigned af[2][4];
            int c0 = kk * 16 + qid * 2;
#pragma unroll
            for (int mt = 0; mt < 2; mt++) {
                int r = wm * 32 + mt * 16 + grp;
                af[mt][0] = *(const unsigned*)&Th[r * P2S + c0];
                af[mt][1] = *(const unsigned*)&Th[(r + 8) * P2S + c0];
                af[mt][2] = *(const unsigned*)&Th[r * P2S + c0 + 8];
                af[mt][3] = *(const unsigned*)&Th[(r + 8) * P2S + c0 + 8];
            }
#pragma unroll
            for (int nt = 0; nt < 4; nt++) {
                int c = wn * 32 + nt * 8 + grp;
                unsigned b0 = *(const unsigned*)&Vh[c * P2S + c0];
                unsigned b1 = *(const unsigned*)&Vh[c * P2S + c0 + 8];
#pragma unroll
                for (int mt = 0; mt < 2; mt++)
                    mma16816(acc2[mt][nt], af[mt], b0, b1);
            }
        }
        __syncthreads();
    }

#pragma unroll
    for (int i = 0; i < 8; i++) {
        float s = tsum[i];
        s += __shfl_xor_sync(0xffffffffu, s, 1);
        s += __shfl_xor_sync(0xffffffffu, s, 2);
        s += __shfl_xor_sync(0xffffffffu, s, 4);
        s += __shfl_xor_sync(0xffffffffu, s, 8);
        if (tx == 0) tsums[ty * 8 + i] = s;
    }
    __syncthreads();

    // epilogue: out = (sumv + acc) / (2048 + sum t) -> fp16
#pragma unroll
    for (int mt = 0; mt < 2; mt++) {
        int rl0 = wm * 32 + mt * 16 + grp;
        float r0 = 1.0f / (2048.0f + tsums[rl0]);
        float r1 = 1.0f / (2048.0f + tsums[rl0 + 8]);
#pragma unroll
        for (int nt = 0; nt < 4; nt++) {
            int dcol = wn * 32 + nt * 8 + qid * 2;
            float sv0 = sumv[bh * DK + dcol];
            float sv1 = sumv[bh * DK + dcol + 1];
            int c = h * DK + dcol;
            size_t o0 = ((size_t)(b * S_ + q0 + rl0)) * D_ + c;
            size_t o1 = ((size_t)(b * S_ + q0 + rl0 + 8)) * D_ + c;
            *(__half2*)&aout[o0] = __floats2half2_rn((sv0 + acc2[mt][nt][0]) * r0,
                                                     (sv1 + acc2[mt][nt][1]) * r0);
            *(__half2*)&aout[o1] = __floats2half2_rn((sv0 + acc2[mt][nt][2]) * r1,
                                                     (sv1 + acc2[mt][nt][3]) * r1);
        }
    }
}

// ---------------- launch ----------------
extern "C" void kernel_launch(void* const* d_in, const int* in_sizes, int n_in,
                              void* d_out, int out_size) {
    const float* x  = (const float*)d_in[0];
    const float* fc = (const float*)d_in[1];
    const float* fs = (const float*)d_in[2];
    const float* W[4] = {(const float*)d_in[3], (const float*)d_in[4],
                         (const float*)d_in[5], (const float*)d_in[6]};
    float* out = (float*)d_out;

    float *v, *sumvp;
    __half *xh, *ah, *wt, *qh, *kh, *vth;
    cudaGetSymbolAddress((void**)&v, g_v);
    cudaGetSymbolAddress((void**)&sumvp, g_sumv);
    cudaGetSymbolAddress((void**)&xh, g_xh);
    cudaGetSymbolAddress((void**)&ah, g_ah);
    cudaGetSymbolAddress((void**)&wt, g_wt);
    cudaGetSymbolAddress((void**)&qh, g_qh);
    cudaGetSymbolAddress((void**)&kh, g_kh);
    cudaGetSymbolAddress((void**)&vth, g_vth);

    cudaFuncSetAttribute(gemm_f16, cudaFuncAttributeMaxDynamicSharedMemorySize, G2SMEM);
    cudaFuncSetAttribute(gemm_rope2, cudaFuncAttributeMaxDynamicSharedMemorySize, G2SMEM);
    cudaFuncSetAttribute(attn_fused, cudaFuncAttributeMaxDynamicSharedMemorySize, FASMEM);

    convX<<<(MS_ * D_) / 256, 256>>>(x, xh);
    convWT4<<<dim3(32, 32, 4), 256>>>(W[0], W[1], W[2], W[3], wt);

    dim3 ggrid(8, 32);
    gemm_rope2<<<dim3(8, 32, 2), 256, G2SMEM>>>(xh, wt, fc, fs, qh, kh);
    gemm_f16<<<ggrid, 256, G2SMEM>>>(xh, wt + 2 * (size_t)D_ * D_, v);

    vtrans<<<dim3(S_ / 32, DK / 32, BH_), 256>>>(v, vth);
    sumv_kernel<<<BH_, 256>>>(v, sumvp);

    attn_fused<<<dim3(S_ / 128, BH_), 256, FASMEM>>>(qh, kh, vth, sumvp, ah);

    gemm_f16<<<ggrid, 256, G2SMEM>>>(ah, wt + 3 * (size_t)D_ * D_, out);
}

// round 14
// speedup vs baseline: 1.0219x; 1.0219x over previous
#include <cuda_runtime.h>
#include <cuda_bf16.h>
#include <cuda_fp16.h>
#include <math.h>

#define B_  2
#define S_  2048
#define D_  1024
#define H_  16
#define DK  64
#define BH_ (B_*H_)
#define MS_ (B_*S_)          // 4096 rows

// ---------------- scratch (static device arrays; no cudaMalloc) ----------------
__device__ float g_v[(size_t)MS_*D_];
__device__ __half g_sh[(size_t)BH_*S_*S_];      // u = exp(s/8), fp16 (256 MB)
__device__ float g_sumv[BH_*DK];
__device__ __half g_xh[(size_t)MS_*D_];          // x fp16
__device__ __half g_ah[(size_t)MS_*D_];          // attn fp16
__device__ __half g_wt[4][(size_t)D_*D_];        // W^T fp16 ([n][k])
__device__ __half g_qh[(size_t)MS_*D_];          // roped q fp16
__device__ __half g_kh[(size_t)MS_*D_];          // roped k fp16
__device__ __half g_vth[(size_t)BH_*DK*S_];      // V^T fp16 [b*h][dk][s]

// ================= helpers =================
__device__ __forceinline__ unsigned smem_u32(const void* p) {
    unsigned a;
    asm("{ .reg .u64 t; cvta.to.shared.u64 t, %1; cvt.u32.u64 %0, t; }" : "=r"(a) : "l"(p));
    return a;
}
__device__ __forceinline__ void cp16(unsigned saddr, const void* gaddr) {
    asm volatile("cp.async.cg.shared.global [%0], [%1], 16;" :: "r"(saddr), "l"(gaddr));
}
__device__ __forceinline__ void cp_commit() { asm volatile("cp.async.commit_group;"); }
template <int N>
__device__ __forceinline__ void cp_wait() { asm volatile("cp.async.wait_group %0;" :: "n"(N)); }

__device__ __forceinline__ void mma16816(float* c, const unsigned* a, unsigned b0, unsigned b1) {
    asm volatile("mma.sync.aligned.m16n8k16.row.col.f32.f16.f16.f32 "
                 "{%0,%1,%2,%3}, {%4,%5,%6,%7}, {%8,%9}, {%0,%1,%2,%3};"
                 : "+f"(c[0]), "+f"(c[1]), "+f"(c[2]), "+f"(c[3])
                 : "r"(a[0]), "r"(a[1]), "r"(a[2]), "r"(a[3]), "r"(b0), "r"(b1));
}

// ================= convert / transform kernels =================
__global__ void convX(const float* __restrict__ X, __half* __restrict__ out) {
    int i = blockIdx.x * 256 + threadIdx.x;
    out[i] = __float2half(X[i]);
}

// batched: W[z][k][n] -> WT fp16 [z][n][k]
__global__ void convWT4(const float* __restrict__ W0, const float* __restrict__ W1,
                        const float* __restrict__ W2, const float* __restrict__ W3,
                        __half* __restrict__ wt) {
    __shared__ float t[32][33];
    const float* Ws[4] = {W0, W1, W2, W3};
    const float* W = Ws[blockIdx.z];
    __half* dst = wt + (size_t)blockIdx.z * D_ * D_;
    int bx = blockIdx.x * 32, by = blockIdx.y * 32;
    int tx = threadIdx.x & 31, ty = threadIdx.x >> 5;
#pragma unroll
    for (int i = 0; i < 32; i += 8)
        t[ty + i][tx] = W[(size_t)(by + ty + i) * 1024 + bx + tx];
    __syncthreads();
#pragma unroll
    for (int i = 0; i < 32; i += 8)
        dst[(size_t)(bx + ty + i) * 1024 + by + tx] = __float2half(t[tx][ty + i]);
}

// V [b][s][h][dk] fp32 -> V^T [b*h][dk][s] fp16
__global__ void vtrans(const float* __restrict__ v, __half* __restrict__ vth) {
    __shared__ float t[32][33];
    int s0 = blockIdx.x * 32, d0 = blockIdx.y * 32;
    int bh = blockIdx.z, b = bh >> 4, h = bh & 15;
    int tx = threadIdx.x & 31, ty = threadIdx.x >> 5;
#pragma unroll
    for (int i = 0; i < 32; i += 8)
        t[ty + i][tx] = v[((size_t)(b * S_ + s0 + ty + i)) * D_ + h * DK + d0 + tx];
    __syncthreads();
#pragma unroll
    for (int i = 0; i < 32; i += 8)
        vth[((size_t)bh * DK + d0 + ty + i) * S_ + s0 + tx] = __float2half(t[tx][ty + i]);
}

// sumv[bh][d] = sum_s v[b][s][h][d]  (exact fp32)
__global__ void sumv_kernel(const float* __restrict__ v, float* __restrict__ sumv) {
    int bh = blockIdx.x, b = bh >> 4, h = bh & 15;
    int d = threadIdx.x & 63, sc = threadIdx.x >> 6;
    float s = 0.f;
    for (int i = 0; i < 512; i++)
        s += v[((size_t)(b * S_ + sc * 512 + i)) * D_ + h * DK + d];
    __shared__ float red[256];
    red[threadIdx.x] = s;
    __syncthreads();
    if (sc == 0) sumv[bh * DK + d] = red[d] + red[64 + d] + red[128 + d] + red[192 + d];
}

// ================= 1-term fp16 GEMM, K-chunk 32, 3-stage pipeline =================
#define SA    40                    // smem row stride in halves (80 B)
#define TILEB (128 * SA * 2)        // 10240 B per tile
#define STG   (2 * TILEB)           // 20480 B per stage (A + B)
#define G3SMEM (3 * STG)            // 61440 B, 3-stage

#define GEMM_LOAD_CHUNK(stage, kchunk)                                              \
    {                                                                               \
        _Pragma("unroll")                                                           \
        for (int t = 0; t < 2; t++)                                                 \
            _Pragma("unroll")                                                       \
            for (int u = 0; u < 2; u++) {                                           \
                int idx = tid * 2 + u;                                              \
                int row = idx >> 2, seg = idx & 3;                                  \
                cp16(sb + (stage) * STG + t * TILEB + row * 80 + seg * 16,          \
                     srcs[t] + (size_t)(r0s[t] + row) * 1024 + (kchunk) * 32 + seg * 8); \
            }                                                                       \
        cp_commit();                                                                \
    }

#define GEMM_MAIN3(ACCUM)                                                           \
    GEMM_LOAD_CHUNK(0, 0)                                                           \
    GEMM_LOAD_CHUNK(1, 1)                                                           \
    for (int ch = 0; ch < 32; ch++) {                                               \
        const int st = ch % 3;                                                      \
        if (ch < 30) {                                                              \
            GEMM_LOAD_CHUNK((ch + 2) % 3, ch + 2)                                   \
            cp_wait<2>();                                                           \
        } else if (ch == 30) {                                                      \
            cp_wait<1>();                                                           \
        } else {                                                                    \
            cp_wait<0>();                                                           \
        }                                                                           \
        __syncthreads();                                                            \
        const __half* Ah = (const __half*)(smc + st * STG);                         \
        const __half* Bh = Ah + 128 * SA;                                           \
        _Pragma("unroll")                                                           \
        for (int kk = 0; kk < 32; kk += 16) {                                       \
            unsigned af[2][4];                                                      \
            _Pragma("unroll")                                                       \
            for (int mt = 0; mt < 2; mt++) {                                        \
                int r = wm * 32 + mt * 16 + grp;                                    \
                af[mt][0] = *(const unsigned*)&Ah[r * SA + kk + qid * 2];           \
                af[mt][1] = *(const unsigned*)&Ah[(r + 8) * SA + kk + qid * 2];     \
                af[mt][2] = *(const unsigned*)&Ah[r * SA + kk + 8 + qid * 2];       \
                af[mt][3] = *(const unsigned*)&Ah[(r + 8) * SA + kk + 8 + qid * 2]; \
            }                                                                       \
            _Pragma("unroll")                                                       \
            for (int nt = 0; nt < 8; nt++) {                                        \
                int c = wn * 64 + nt * 8 + grp;                                     \
                unsigned b0 = *(const unsigned*)&Bh[c * SA + kk + qid * 2];         \
                unsigned b1 = *(const unsigned*)&Bh[c * SA + kk + 8 + qid * 2];     \
                _Pragma("unroll")                                                   \
                for (int mt = 0; mt < 2; mt++)                                      \
                    mma16816(ACCUM[mt][nt], af[mt], b0, b1);                        \
            }                                                                       \
        }                                                                           \
        __syncthreads();                                                            \
    }

// plain: C fp32 = A fp16 @ W^T fp16
__global__ __launch_bounds__(256, 2) void gemm_f16(const __half* __restrict__ Ah_,
                                                   const __half* __restrict__ Bh_,
                                                   float* __restrict__ C) {
    extern __shared__ char smc[];
    const int tid = threadIdx.x, lane = tid & 31, wid = tid >> 5;
    const int wm = wid & 3, wn = wid >> 2;
    const int grp = lane >> 2, qid = lane & 3;
    const int m0 = blockIdx.y * 128, n0 = blockIdx.x * 128;
    const unsigned sb = smem_u32(smc);

    const __half* srcs[2] = {Ah_, Bh_};
    const int r0s[2] = {m0, n0};

    float acc[2][8][4];
#pragma unroll
    for (int mt = 0; mt < 2; mt++)
#pragma unroll
        for (int nt = 0; nt < 8; nt++)
#pragma unroll
            for (int e = 0; e < 4; e++) acc[mt][nt][e] = 0.f;

    GEMM_MAIN3(acc)

#pragma unroll
    for (int mt = 0; mt < 2; mt++) {
        int r = m0 + wm * 32 + mt * 16 + grp;
#pragma unroll
        for (int nt = 0; nt < 8; nt++) {
            int c = n0 + wn * 64 + nt * 8 + qid * 2;
            *(float2*)&C[(size_t)r * 1024 + c]       = make_float2(acc[mt][nt][0], acc[mt][nt][1]);
            *(float2*)&C[(size_t)(r + 8) * 1024 + c] = make_float2(acc[mt][nt][2], acc[mt][nt][3]);
        }
    }
}

// z-batched (Wq, Wk) GEMM with fused RoPE epilogue -> fp16
__global__ __launch_bounds__(256, 2) void gemm_rope2(const __half* __restrict__ Ah_,
                                                     const __half* __restrict__ wt,
                                                     const float* __restrict__ fc,
                                                     const float* __restrict__ fs,
                                                     __half* __restrict__ qdst,
                                                     __half* __restrict__ kdst) {
    extern __shared__ char smc[];
    const int tid = threadIdx.x, lane = tid & 31, wid = tid >> 5;
    const int wm = wid & 3, wn = wid >> 2;
    const int grp = lane >> 2, qid = lane & 3;
    const int m0 = blockIdx.y * 128, n0 = blockIdx.x * 128;
    const unsigned sb = smem_u32(smc);

    const __half* Bh_ = wt + (size_t)blockIdx.z * D_ * D_;
    __half* dst = blockIdx.z ? kdst : qdst;

    const __half* srcs[2] = {Ah_, Bh_};
    const int r0s[2] = {m0, n0};

    float acc[2][8][4];
#pragma unroll
    for (int mt = 0; mt < 2; mt++)
#pragma unroll
        for (int nt = 0; nt < 8; nt++)
#pragma unroll
            for (int e = 0; e < 4; e++) acc[mt][nt][e] = 0.f;

    GEMM_MAIN3(acc)

    // fused RoPE epilogue -> fp16
#pragma unroll
    for (int mt = 0; mt < 2; mt++) {
        int r = m0 + wm * 32 + mt * 16 + grp;
        int s = r & (S_ - 1);
#pragma unroll
        for (int nt = 0; nt < 8; nt++) {
            int c = n0 + wn * 64 + nt * 8 + qid * 2;
            int ii = (c & 63) >> 1;
            float c0 = fc[s * 32 + ii],       s0 = fs[s * 32 + ii];
            float c1 = fc[(s + 8) * 32 + ii], s1 = fs[(s + 8) * 32 + ii];
            float re0 = acc[mt][nt][0], im0 = acc[mt][nt][1];
            float re1 = acc[mt][nt][2], im1 = acc[mt][nt][3];
            __half2 p0, p1;
            p0.x = __float2half(re0 * c0 - im0 * s0);
            p0.y = __float2half(re0 * s0 + im0 * c0);
            p1.x = __float2half(re1 * c1 - im1 * s1);
            p1.y = __float2half(re1 * s1 + im1 * c1);
            *(__half2*)&dst[(size_t)r * 1024 + c]       = p0;
            *(__half2*)&dst[(size_t)(r + 8) * 1024 + c] = p1;
        }
    }
}

// ================= fused attention: pass1 + pass2 =================
#define P1S   72
#define P1ROW (P1S * 2)
#define P1T   (128 * P1ROW)   // 18432
#define P2S   136
#define P2ROW (P2S * 2)
#define P2TT  (128 * P2ROW)   // 34816
#define P2VT  (64 * P2ROW)    // 17408
#define FA_ZBUF (4 * P1T)           // 73728
#define FA_SZ   (4 * P1T + 1024)
#define FASMEM  (4 * P1T + 2048)    // 75776

__global__ __launch_bounds__(256, 2) void attn_fused(const __half* __restrict__ qh,
                                                     const __half* __restrict__ kh,
                                                     const __half* __restrict__ vth,
                                                     const float* __restrict__ sumv,
                                                     __half* __restrict__ aout) {
    extern __shared__ char smc[];
    const unsigned sb = smem_u32(smc);
    const int tid = threadIdx.x, lane = tid & 31, wid = tid >> 5;
    const int wm = wid & 3, wn = wid >> 2;
    const int grp = lane >> 2, qid = lane & 3;
    const int bh = blockIdx.y, b = bh >> 4, h = bh & 15;
    const int q0 = blockIdx.x * 128;
    const int ty = tid >> 4, tx = tid & 15;
    float* zbuf = (float*)(smc + FA_ZBUF);
    float* sz   = (float*)(smc + FA_SZ);

    // ======== phase A: u = exp(QK^T/8) -> fp16 gmem, z = sum u -> smem ========
    // K stages at P1T*(1 + kt%3); Q at 0. Prologue: {Q,K0} then {K1}.
    {
#pragma unroll
        for (int u = 0; u < 4; u++) {
            int idx = tid * 4 + u;
            int row = idx >> 3, ch = idx & 7;
            cp16(sb + row * P1ROW + ch * 16,
                 qh + ((size_t)(b * S_ + q0 + row)) * D_ + h * DK + ch * 8);
        }
#pragma unroll
        for (int u = 0; u < 4; u++) {
            int idx = tid * 4 + u;
            int row = idx >> 3, ch = idx & 7;
            cp16(sb + P1T + row * P1ROW + ch * 16,
                 kh + ((size_t)(b * S_ + row)) * D_ + h * DK + ch * 8);
        }
        cp_commit();
#pragma unroll
        for (int u = 0; u < 4; u++) {
            int idx = tid * 4 + u;
            int row = idx >> 3, ch = idx & 7;
            cp16(sb + 2 * P1T + row * P1ROW + ch * 16,
                 kh + ((size_t)(b * S_ + 128 + row)) * D_ + h * DK + ch * 8);
        }
        cp_commit();
    }
    cp_wait<1>();       // {Q,K0} done; K1 may be in flight
    __syncthreads();

    unsigned qf[2][4][4];
    {
        const __half* Qh = (const __half*)smc;
#pragma unroll
        for (int mt = 0; mt < 2; mt++) {
            int r = wm * 32 + mt * 16 + grp;
#pragma unroll
            for (int kk = 0; kk < 4; kk++) {
                int c0 = kk * 16 + qid * 2;
                qf[mt][kk][0] = *(const unsigned*)&Qh[r * P1S + c0];
                qf[mt][kk][1] = *(const unsigned*)&Qh[(r + 8) * P1S + c0];
                qf[mt][kk][2] = *(const unsigned*)&Qh[r * P1S + c0 + 8];
                qf[mt][kk][3] = *(const unsigned*)&Qh[(r + 8) * P1S + c0 + 8];
            }
        }
    }

    float zacc[2][2] = {{0.f, 0.f}, {0.f, 0.f}};

    for (int kt = 0; kt < 16; kt++) {
        const int st = kt % 3;
        if (kt < 14) {
            const int ns = (kt + 2) % 3;
#pragma unroll
            for (int u = 0; u < 4; u++) {
                int idx = tid * 4 + u;
                int row = idx >> 3, ch = idx & 7;
                cp16(sb + (1 + ns) * P1T + row * P1ROW + ch * 16,
                     kh + ((size_t)(b * S_ + (kt + 2) * 128 + row)) * D_ + h * DK + ch * 8);
            }
            cp_commit();
            cp_wait<2>();
        } else if (kt == 14) {
            cp_wait<1>();
        } else {
            cp_wait<0>();
        }
        __syncthreads();

        const __half* Kh = (const __half*)(smc + (1 + st) * P1T);

        float acc[2][8][4];
#pragma unroll
        for (int mt = 0; mt < 2; mt++)
#pragma unroll
            for (int nt = 0; nt < 8; nt++)
#pragma unroll
                for (int e = 0; e < 4; e++) acc[mt][nt][e] = 0.f;

#pragma unroll
        for (int kk = 0; kk < 4; kk++) {
#pragma unroll
            for (int nt = 0; nt < 8; nt++) {
                int c = wn * 64 + nt * 8 + grp;
                int c0 = kk * 16 + qid * 2;
                unsigned b0 = *(const unsigned*)&Kh[c * P1S + c0];
                unsigned b1 = *(const unsigned*)&Kh[c * P1S + c0 + 8];
#pragma unroll
                for (int mt = 0; mt < 2; mt++)
                    mma16816(acc[mt][nt], qf[mt][kk], b0, b1);
            }
        }

        // epilogue: u = exp(s/8) -> fp16 gmem, z += u
#pragma unroll
        for (int mt = 0; mt < 2; mt++) {
            int r = q0 + wm * 32 + mt * 16 + grp;
#pragma unroll
            for (int nt = 0; nt < 8; nt++) {
                int c = kt * 128 + wn * 64 + nt * 8 + qid * 2;
                float u0 = __expf(acc[mt][nt][0] * 0.125f);
                float u1 = __expf(acc[mt][nt][1] * 0.125f);
                float u2 = __expf(acc[mt][nt][2] * 0.125f);
                float u3 = __expf(acc[mt][nt][3] * 0.125f);
                *(__half2*)&g_sh[((size_t)bh * S_ + r) * S_ + c]     = __floats2half2_rn(u0, u1);
                *(__half2*)&g_sh[((size_t)bh * S_ + r + 8) * S_ + c] = __floats2half2_rn(u2, u3);
                zacc[mt][0] += u0 + u1;
                zacc[mt][1] += u2 + u3;
            }
        }
        __syncthreads();
    }

#pragma unroll
    for (int mt = 0; mt < 2; mt++)
#pragma unroll
        for (int hf = 0; hf < 2; hf++) {
            float z = zacc[mt][hf];
            z += __shfl_xor_sync(0xffffffffu, z, 1);
            z += __shfl_xor_sync(0xffffffffu, z, 2);
            if (qid == 0) zbuf[wn * 128 + wm * 32 + mt * 16 + hf * 8 + grp] = z;
        }
    __syncthreads();
    if (tid < 128) sz[tid] = zbuf[tid] + zbuf[128 + tid];
    __syncthreads();

    // ======== phase B: p = u/z; t = p + p^2/2; out = (sumv + tV)/(2048+sum t) ====
    __half* Th = (__half*)smc;
    const __half* Vh = (const __half*)(smc + P2TT);
    float* tsums = (float*)(smc + P2TT + P2VT);

    float iz[8], tsum[8];
#pragma unroll
    for (int i = 0; i < 8; i++) {
        iz[i] = 1.0f / sz[ty * 8 + i];
        tsum[i] = 0.f;
    }

    float acc2[2][4][4];
#pragma unroll
    for (int mt = 0; mt < 2; mt++)
#pragma unroll
        for (int nt = 0; nt < 4; nt++)
#pragma unroll
            for (int e = 0; e < 4; e++) acc2[mt][nt][e] = 0.f;

    for (int kt = 0; kt < 16; kt++) {
        const int k0 = kt * 128;
        {
#pragma unroll
            for (int u = 0; u < 4; u++) {
                int idx = tid * 4 + u;                 // 0..1023
                int row = idx >> 4, ch = idx & 15;
                cp16(sb + P2TT + row * P2ROW + ch * 16,
                     vth + ((size_t)bh * DK + row) * S_ + k0 + ch * 8);
            }
            cp_commit();
        }
        // t tile from fp16 u values — no MUFU here
#pragma unroll
        for (int i = 0; i < 8; i++) {
            int r = ty * 8 + i;
#pragma unroll
            for (int hf = 0; hf < 2; hf++) {
                int c = hf * 64 + tx * 4;
                struct alignas(8) H4 { __half2 a, b; };
                H4 s4 = *(const H4*)&g_sh[((size_t)bh * S_ + q0 + r) * S_ + k0 + c];
                float2 f01 = __half22float2(s4.a);
                float2 f23 = __half22float2(s4.b);
                float p0 = f01.x * iz[i];
                float p1 = f01.y * iz[i];
                float p2 = f23.x * iz[i];
                float p3 = f23.y * iz[i];
                float t0 = fmaf(0.5f * p0, p0, p0);   // expm1(p), p <= ~0.006
                float t1 = fmaf(0.5f * p1, p1, p1);
                float t2 = fmaf(0.5f * p2, p2, p2);
                float t3 = fmaf(0.5f * p3, p3, p3);
                tsum[i] += (t0 + t1) + (t2 + t3);
                *(__half2*)&Th[r * P2S + c]     = __floats2half2_rn(t0, t1);
                *(__half2*)&Th[r * P2S + c + 2] = __floats2half2_rn(t2, t3);
            }
        }
        cp_wait<0>();
        __syncthreads();

#pragma unroll
        for (int kk = 0; kk < 8; kk++) {
            unsigned af[2][4];
            int c0 = kk * 16 + qid * 2;
#pragma unroll
            for (int mt = 0; mt < 2; mt++) {
                int r = wm * 32 + mt * 16 + grp;
                af[mt][0] = *(const unsigned*)&Th[r * P2S + c0];
                af[mt][1] = *(const unsigned*)&Th[(r + 8) * P2S + c0];
                af[mt][2] = *(const unsigned*)&Th[r * P2S + c0 + 8];
                af[mt][3] = *(const unsigned*)&Th[(r + 8) * P2S + c0 + 8];
            }
#pragma unroll
            for (int nt = 0; nt < 4; nt++) {
                int c = wn * 32 + nt * 8 + grp;
                unsigned b0 = *(const unsigned*)&Vh[c * P2S + c0];
                unsigned b1 = *(const unsigned*)&Vh[c * P2S + c0 + 8];
#pragma unroll
                for (int mt = 0; mt < 2; mt++)
                    mma16816(acc2[mt][nt], af[mt], b0, b1);
            }
        }
        __syncthreads();
    }

#pragma unroll
    for (int i = 0; i < 8; i++) {
        float s = tsum[i];
        s += __shfl_xor_sync(0xffffffffu, s, 1);
        s += __shfl_xor_sync(0xffffffffu, s, 2);
        s += __shfl_xor_sync(0xffffffffu, s, 4);
        s += __shfl_xor_sync(0xffffffffu, s, 8);
        if (tx == 0) tsums[ty * 8 + i] = s;
    }
    __syncthreads();

    // epilogue: out = (sumv + acc) / (2048 + sum t) -> fp16
#pragma unroll
    for (int mt = 0; mt < 2; mt++) {
        int rl0 = wm * 32 + mt * 16 + grp;
        float r0 = 1.0f / (2048.0f + tsums[rl0]);
        float r1 = 1.0f / (2048.0f + tsums[rl0 + 8]);
#pragma unroll
        for (int nt = 0; nt < 4; nt++) {
            int dcol = wn * 32 + nt * 8 + qid * 2;
            float sv0 = sumv[bh * DK + dcol];
            float sv1 = sumv[bh * DK + dcol + 1];
            int c = h * DK + dcol;
            size_t o0 = ((size_t)(b * S_ + q0 + rl0)) * D_ + c;
            size_t o1 = ((size_t)(b * S_ + q0 + rl0 + 8)) * D_ + c;
            *(__half2*)&aout[o0] = __floats2half2_rn((sv0 + acc2[mt][nt][0]) * r0,
                                                     (sv1 + acc2[mt][nt][1]) * r0);
            *(__half2*)&aout[o1] = __floats2half2_rn((sv0 + acc2[mt][nt][2]) * r1,
                                                     (sv1 + acc2[mt][nt][3]) * r1);
        }
    }
}

// ---------------- launch ----------------
extern "C" void kernel_launch(void* const* d_in, const int* in_sizes, int n_in,
                              void* d_out, int out_size) {
    const float* x  = (const float*)d_in[0];
    const float* fc = (const float*)d_in[1];
    const float* fs = (const float*)d_in[2];
    const float* W[4] = {(const float*)d_in[3], (const float*)d_in[4],
                         (const float*)d_in[5], (const float*)d_in[6]};
    float* out = (float*)d_out;

    float *v, *sumvp;
    __half *xh, *ah, *wt, *qh, *kh, *vth;
    cudaGetSymbolAddress((void**)&v, g_v);
    cudaGetSymbolAddress((void**)&sumvp, g_sumv);
    cudaGetSymbolAddress((void**)&xh, g_xh);
    cudaGetSymbolAddress((void**)&ah, g_ah);
    cudaGetSymbolAddress((void**)&wt, g_wt);
    cudaGetSymbolAddress((void**)&qh, g_qh);
    cudaGetSymbolAddress((void**)&kh, g_kh);
    cudaGetSymbolAddress((void**)&vth, g_vth);

    cudaFuncSetAttribute(gemm_f16, cudaFuncAttributeMaxDynamicSharedMemorySize, G3SMEM);
    cudaFuncSetAttribute(gemm_rope2, cudaFuncAttributeMaxDynamicSharedMemorySize, G3SMEM);
    cudaFuncSetAttribute(attn_fused, cudaFuncAttributeMaxDynamicSharedMemorySize, FASMEM);

    convX<<<(MS_ * D_) / 256, 256>>>(x, xh);
    convWT4<<<dim3(32, 32, 4), 256>>>(W[0], W[1], W[2], W[3], wt);

    dim3 ggrid(8, 32);
    gemm_rope2<<<dim3(8, 32, 2), 256, G3SMEM>>>(xh, wt, fc, fs, qh, kh);
    gemm_f16<<<ggrid, 256, G3SMEM>>>(xh, wt + 2 * (size_t)D_ * D_, v);

    vtrans<<<dim3(S_ / 32, DK / 32, BH_), 256>>>(v, vth);
    sumv_kernel<<<BH_, 256>>>(v, sumvp);

    attn_fused<<<dim3(S_ / 128, BH_), 256, FASMEM>>>(qh, kh, vth, sumvp, ah);

    gemm_f16<<<ggrid, 256, G3SMEM>>>(ah, wt + 3 * (size_t)D_ * D_, out);
}

// round 15
// speedup vs baseline: 1.2371x; 1.2106x over previous
#include <cuda_runtime.h>
#include <cuda_bf16.h>
#include <cuda_fp16.h>
#include <math.h>

#define B_  2
#define S_  2048
#define D_  1024
#define H_  16
#define DK  64
#define BH_ (B_*H_)
#define MS_ (B_*S_)          // 4096 rows

// ---------------- scratch (static device arrays; no cudaMalloc) ----------------
__device__ float g_v[(size_t)MS_*D_];
__device__ float g_sumv[BH_*DK];
__device__ __half g_xh[(size_t)MS_*D_];          // x fp16
__device__ __half g_ah[(size_t)MS_*D_];          // attn fp16
__device__ __half g_wt[4][(size_t)D_*D_];        // W^T fp16 ([n][k])
__device__ __half g_qh[(size_t)MS_*D_];          // roped q fp16
__device__ __half g_kh[(size_t)MS_*D_];          // roped k fp16
__device__ __half g_vth[(size_t)BH_*DK*S_];      // V^T fp16 [b*h][dk][s]

// ================= helpers =================
__device__ __forceinline__ unsigned smem_u32(const void* p) {
    unsigned a;
    asm("{ .reg .u64 t; cvta.to.shared.u64 t, %1; cvt.u32.u64 %0, t; }" : "=r"(a) : "l"(p));
    return a;
}
__device__ __forceinline__ void cp16(unsigned saddr, const void* gaddr) {
    asm volatile("cp.async.cg.shared.global [%0], [%1], 16;" :: "r"(saddr), "l"(gaddr));
}
__device__ __forceinline__ void cp_commit() { asm volatile("cp.async.commit_group;"); }
template <int N>
__device__ __forceinline__ void cp_wait() { asm volatile("cp.async.wait_group %0;" :: "n"(N)); }

__device__ __forceinline__ void mma16816(float* c, const unsigned* a, unsigned b0, unsigned b1) {
    asm volatile("mma.sync.aligned.m16n8k16.row.col.f32.f16.f16.f32 "
                 "{%0,%1,%2,%3}, {%4,%5,%6,%7}, {%8,%9}, {%0,%1,%2,%3};"
                 : "+f"(c[0]), "+f"(c[1]), "+f"(c[2]), "+f"(c[3])
                 : "r"(a[0]), "r"(a[1]), "r"(a[2]), "r"(a[3]), "r"(b0), "r"(b1));
}

// ================= convert / transform kernels =================
__global__ void convX(const float* __restrict__ X, __half* __restrict__ out) {
    int i = blockIdx.x * 256 + threadIdx.x;
    out[i] = __float2half(X[i]);
}

// batched: W[z][k][n] -> WT fp16 [z][n][k]
__global__ void convWT4(const float* __restrict__ W0, const float* __restrict__ W1,
                        const float* __restrict__ W2, const float* __restrict__ W3,
                        __half* __restrict__ wt) {
    __shared__ float t[32][33];
    const float* Ws[4] = {W0, W1, W2, W3};
    const float* W = Ws[blockIdx.z];
    __half* dst = wt + (size_t)blockIdx.z * D_ * D_;
    int bx = blockIdx.x * 32, by = blockIdx.y * 32;
    int tx = threadIdx.x & 31, ty = threadIdx.x >> 5;
#pragma unroll
    for (int i = 0; i < 32; i += 8)
        t[ty + i][tx] = W[(size_t)(by + ty + i) * 1024 + bx + tx];
    __syncthreads();
#pragma unroll
    for (int i = 0; i < 32; i += 8)
        dst[(size_t)(bx + ty + i) * 1024 + by + tx] = __float2half(t[tx][ty + i]);
}

// V [b][s][h][dk] fp32 -> V^T [b*h][dk][s] fp16
__global__ void vtrans(const float* __restrict__ v, __half* __restrict__ vth) {
    __shared__ float t[32][33];
    int s0 = blockIdx.x * 32, d0 = blockIdx.y * 32;
    int bh = blockIdx.z, b = bh >> 4, h = bh & 15;
    int tx = threadIdx.x & 31, ty = threadIdx.x >> 5;
#pragma unroll
    for (int i = 0; i < 32; i += 8)
        t[ty + i][tx] = v[((size_t)(b * S_ + s0 + ty + i)) * D_ + h * DK + d0 + tx];
    __syncthreads();
#pragma unroll
    for (int i = 0; i < 32; i += 8)
        vth[((size_t)bh * DK + d0 + ty + i) * S_ + s0 + tx] = __float2half(t[tx][ty + i]);
}

// sumv[bh][d] = sum_s v[b][s][h][d]  (exact fp32)
__global__ void sumv_kernel(const float* __restrict__ v, float* __restrict__ sumv) {
    int bh = blockIdx.x, b = bh >> 4, h = bh & 15;
    int d = threadIdx.x & 63, sc = threadIdx.x >> 6;
    float s = 0.f;
    for (int i = 0; i < 512; i++)
        s += v[((size_t)(b * S_ + sc * 512 + i)) * D_ + h * DK + d];
    __shared__ float red[256];
    red[threadIdx.x] = s;
    __syncthreads();
    if (sc == 0) sumv[bh * DK + d] = red[d] + red[64 + d] + red[128 + d] + red[192 + d];
}

// ================= 1-term fp16 GEMM (K-chunk 32, double buffered) =================
#define SA    40
#define TILEB (128 * SA * 2)
#define B1B   (2 * TILEB)
#define G1SMEM (2 * B1B)

#define GEMM_MAINLOOP(ACCUM)                                                        \
    {                                                                               \
        _Pragma("unroll")                                                           \
        for (int t = 0; t < 2; t++)                                                 \
            _Pragma("unroll")                                                       \
            for (int u = 0; u < 2; u++) {                                           \
                int idx = tid * 2 + u;                                              \
                int row = idx >> 2, seg = idx & 3;                                  \
                cp16(sb + t * TILEB + row * 80 + seg * 16,                          \
                     srcs[t] + (size_t)(r0s[t] + row) * 1024 + seg * 8);            \
            }                                                                       \
        cp_commit();                                                                \
    }                                                                               \
    for (int ch = 0; ch < 32; ch++) {                                               \
        const int buf = ch & 1;                                                     \
        if (ch < 31) {                                                              \
            const int k0 = (ch + 1) * 32, nbuf = (ch + 1) & 1;                      \
            _Pragma("unroll")                                                       \
            for (int t = 0; t < 2; t++)                                             \
                _Pragma("unroll")                                                   \
                for (int u = 0; u < 2; u++) {                                       \
                    int idx = tid * 2 + u;                                          \
                    int row = idx >> 2, seg = idx & 3;                              \
                    cp16(sb + nbuf * B1B + t * TILEB + row * 80 + seg * 16,         \
                         srcs[t] + (size_t)(r0s[t] + row) * 1024 + k0 + seg * 8);   \
                }                                                                   \
            cp_commit();                                                            \
            cp_wait<1>();                                                           \
        } else {                                                                    \
            cp_wait<0>();                                                           \
        }                                                                           \
        __syncthreads();                                                            \
        const __half* Ah = (const __half*)(smc + buf * B1B);                        \
        const __half* Bh = Ah + 128 * SA;                                           \
        _Pragma("unroll")                                                           \
        for (int kk = 0; kk < 32; kk += 16) {                                       \
            unsigned af[2][4];                                                      \
            _Pragma("unroll")                                                       \
            for (int mt = 0; mt < 2; mt++) {                                        \
                int r = wm * 32 + mt * 16 + grp;                                    \
                af[mt][0] = *(const unsigned*)&Ah[r * SA + kk + qid * 2];           \
                af[mt][1] = *(const unsigned*)&Ah[(r + 8) * SA + kk + qid * 2];     \
                af[mt][2] = *(const unsigned*)&Ah[r * SA + kk + 8 + qid * 2];       \
                af[mt][3] = *(const unsigned*)&Ah[(r + 8) * SA + kk + 8 + qid * 2]; \
            }                                                                       \
            _Pragma("unroll")                                                       \
            for (int nt = 0; nt < 8; nt++) {                                        \
                int c = wn * 64 + nt * 8 + grp;                                     \
                unsigned b0 = *(const unsigned*)&Bh[c * SA + kk + qid * 2];         \
                unsigned b1 = *(const unsigned*)&Bh[c * SA + kk + 8 + qid * 2];     \
                _Pragma("unroll")                                                   \
                for (int mt = 0; mt < 2; mt++)                                      \
                    mma16816(ACCUM[mt][nt], af[mt], b0, b1);                        \
            }                                                                       \
        }                                                                           \
        __syncthreads();                                                            \
    }

__global__ __launch_bounds__(256, 2) void gemm_f16(const __half* __restrict__ Ah_,
                                                   const __half* __restrict__ Bh_,
                                                   float* __restrict__ C) {
    extern __shared__ char smc[];
    const int tid = threadIdx.x, lane = tid & 31, wid = tid >> 5;
    const int wm = wid & 3, wn = wid >> 2;
    const int grp = lane >> 2, qid = lane & 3;
    const int m0 = blockIdx.y * 128, n0 = blockIdx.x * 128;
    const unsigned sb = smem_u32(smc);

    const __half* srcs[2] = {Ah_, Bh_};
    const int r0s[2] = {m0, n0};

    float acc[2][8][4];
#pragma unroll
    for (int mt = 0; mt < 2; mt++)
#pragma unroll
        for (int nt = 0; nt < 8; nt++)
#pragma unroll
            for (int e = 0; e < 4; e++) acc[mt][nt][e] = 0.f;

    GEMM_MAINLOOP(acc)

#pragma unroll
    for (int mt = 0; mt < 2; mt++) {
        int r = m0 + wm * 32 + mt * 16 + grp;
#pragma unroll
        for (int nt = 0; nt < 8; nt++) {
            int c = n0 + wn * 64 + nt * 8 + qid * 2;
            *(float2*)&C[(size_t)r * 1024 + c]       = make_float2(acc[mt][nt][0], acc[mt][nt][1]);
            *(float2*)&C[(size_t)(r + 8) * 1024 + c] = make_float2(acc[mt][nt][2], acc[mt][nt][3]);
        }
    }
}

__global__ __launch_bounds__(256, 2) void gemm_rope2(const __half* __restrict__ Ah_,
                                                     const __half* __restrict__ wt,
                                                     const float* __restrict__ fc,
                                                     const float* __restrict__ fs,
                                                     __half* __restrict__ qdst,
                                                     __half* __restrict__ kdst) {
    extern __shared__ char smc[];
    const int tid = threadIdx.x, lane = tid & 31, wid = tid >> 5;
    const int wm = wid & 3, wn = wid >> 2;
    const int grp = lane >> 2, qid = lane & 3;
    const int m0 = blockIdx.y * 128, n0 = blockIdx.x * 128;
    const unsigned sb = smem_u32(smc);

    const __half* Bh_ = wt + (size_t)blockIdx.z * D_ * D_;
    __half* dst = blockIdx.z ? kdst : qdst;

    const __half* srcs[2] = {Ah_, Bh_};
    const int r0s[2] = {m0, n0};

    float acc[2][8][4];
#pragma unroll
    for (int mt = 0; mt < 2; mt++)
#pragma unroll
        for (int nt = 0; nt < 8; nt++)
#pragma unroll
            for (int e = 0; e < 4; e++) acc[mt][nt][e] = 0.f;

    GEMM_MAINLOOP(acc)

#pragma unroll
    for (int mt = 0; mt < 2; mt++) {
        int r = m0 + wm * 32 + mt * 16 + grp;
        int s = r & (S_ - 1);
#pragma unroll
        for (int nt = 0; nt < 8; nt++) {
            int c = n0 + wn * 64 + nt * 8 + qid * 2;
            int ii = (c & 63) >> 1;
            float c0 = fc[s * 32 + ii],       s0 = fs[s * 32 + ii];
            float c1 = fc[(s + 8) * 32 + ii], s1 = fs[(s + 8) * 32 + ii];
            float re0 = acc[mt][nt][0], im0 = acc[mt][nt][1];
            float re1 = acc[mt][nt][2], im1 = acc[mt][nt][3];
            __half2 p0, p1;
            p0.x = __float2half(re0 * c0 - im0 * s0);
            p0.y = __float2half(re0 * s0 + im0 * c0);
            p1.x = __float2half(re1 * c1 - im1 * s1);
            p1.y = __float2half(re1 * s1 + im1 * c1);
            *(__half2*)&dst[(size_t)r * 1024 + c]       = p0;
            *(__half2*)&dst[(size_t)(r + 8) * 1024 + c] = p1;
        }
    }
}

// ================= single-pass fused attention (no score buffer) =================
// out = (sumv + (U@V)/z) / 2049, U = exp(QK^T/8), z = row-sum U
#define P1S   72
#define P1ROW (P1S * 2)       // 144
#define P1T   (128 * P1ROW)   // 18432
#define P2S   136
#define P2ROW (P2S * 2)       // 272
#define ATT_TH (3 * P1T)               // 55296
#define ATT_V  (ATT_TH + 128 * P2ROW)  // 90112
#define ATT_ZB (ATT_V + 64 * P2ROW)    // 107520
#define ATT_SZ (ATT_ZB + 1024)         // 108544
#define FASMEM (ATT_SZ + 512)          // 109056

__global__ __launch_bounds__(256, 2) void attn_fused(const __half* __restrict__ qh,
                                                     const __half* __restrict__ kh,
                                                     const __half* __restrict__ vth,
                                                     const float* __restrict__ sumv,
                                                     __half* __restrict__ aout) {
    extern __shared__ char smc[];
    const unsigned sb = smem_u32(smc);
    const int tid = threadIdx.x, lane = tid & 31, wid = tid >> 5;
    const int wm = wid & 3, wn = wid >> 2;
    const int grp = lane >> 2, qid = lane & 3;
    const int bh = blockIdx.y, b = bh >> 4, h = bh & 15;
    const int q0 = blockIdx.x * 128;
    float* zbuf = (float*)(smc + ATT_ZB);
    float* sz   = (float*)(smc + ATT_SZ);
    __half* Th = (__half*)(smc + ATT_TH);
    const __half* Vh = (const __half*)(smc + ATT_V);

    // prologue: Q tile + K tile 0 (one group)
    {
#pragma unroll
        for (int u = 0; u < 4; u++) {
            int idx = tid * 4 + u;
            int row = idx >> 3, ch = idx & 7;
            cp16(sb + row * P1ROW + ch * 16,
                 qh + ((size_t)(b * S_ + q0 + row)) * D_ + h * DK + ch * 8);
        }
#pragma unroll
        for (int u = 0; u < 4; u++) {
            int idx = tid * 4 + u;
            int row = idx >> 3, ch = idx & 7;
            cp16(sb + P1T + row * P1ROW + ch * 16,
                 kh + ((size_t)(b * S_ + row)) * D_ + h * DK + ch * 8);
        }
        cp_commit();
    }
    cp_wait<0>();
    __syncthreads();

    unsigned qf[2][4][4];
    {
        const __half* Qh = (const __half*)smc;
#pragma unroll
        for (int mt = 0; mt < 2; mt++) {
            int r = wm * 32 + mt * 16 + grp;
#pragma unroll
            for (int kk = 0; kk < 4; kk++) {
                int c0 = kk * 16 + qid * 2;
                qf[mt][kk][0] = *(const unsigned*)&Qh[r * P1S + c0];
                qf[mt][kk][1] = *(const unsigned*)&Qh[(r + 8) * P1S + c0];
                qf[mt][kk][2] = *(const unsigned*)&Qh[r * P1S + c0 + 8];
                qf[mt][kk][3] = *(const unsigned*)&Qh[(r + 8) * P1S + c0 + 8];
            }
        }
    }

    float zacc[2][2] = {{0.f, 0.f}, {0.f, 0.f}};
    float acc1[2][4][4];
#pragma unroll
    for (int mt = 0; mt < 2; mt++)
#pragma unroll
        for (int nt = 0; nt < 4; nt++)
#pragma unroll
            for (int e = 0; e < 4; e++) acc1[mt][nt][e] = 0.f;

    for (int kt = 0; kt < 16; kt++) {
        const int buf = kt & 1;
        // V(kt) load (own group)
        {
#pragma unroll
            for (int u = 0; u < 4; u++) {
                int idx = tid * 4 + u;
                int row = idx >> 4, ch = idx & 15;
                cp16(sb + ATT_V + row * P2ROW + ch * 16,
                     vth + ((size_t)bh * DK + row) * S_ + kt * 128 + ch * 8);
            }
            cp_commit();
        }
        // K(kt+1) prefetch
        if (kt < 15) {
            const int nbuf = (kt + 1) & 1;
#pragma unroll
            for (int u = 0; u < 4; u++) {
                int idx = tid * 4 + u;
                int row = idx >> 3, ch = idx & 7;
                cp16(sb + (1 + nbuf) * P1T + row * P1ROW + ch * 16,
                     kh + ((size_t)(b * S_ + (kt + 1) * 128 + row)) * D_ + h * DK + ch * 8);
            }
            cp_commit();
            cp_wait<2>();     // K(kt) done
        } else {
            cp_wait<1>();     // K(15) done, V(15) in flight
        }
        __syncthreads();

        const __half* Kh = (const __half*)(smc + (1 + buf) * P1T);

        // s-tile = Q @ K^T
        float acc[2][8][4];
#pragma unroll
        for (int mt = 0; mt < 2; mt++)
#pragma unroll
            for (int nt = 0; nt < 8; nt++)
#pragma unroll
                for (int e = 0; e < 4; e++) acc[mt][nt][e] = 0.f;

#pragma unroll
        for (int kk = 0; kk < 4; kk++) {
#pragma unroll
            for (int nt = 0; nt < 8; nt++) {
                int c = wn * 64 + nt * 8 + grp;
                int c0 = kk * 16 + qid * 2;
                unsigned b0 = *(const unsigned*)&Kh[c * P1S + c0];
                unsigned b1 = *(const unsigned*)&Kh[c * P1S + c0 + 8];
#pragma unroll
                for (int mt = 0; mt < 2; mt++)
                    mma16816(acc[mt][nt], qf[mt][kk], b0, b1);
            }
        }

        // u = exp(s/8): z accumulate, store u tile -> smem
#pragma unroll
        for (int mt = 0; mt < 2; mt++) {
            int rl = wm * 32 + mt * 16 + grp;
#pragma unroll
            for (int nt = 0; nt < 8; nt++) {
                int cl = wn * 64 + nt * 8 + qid * 2;
                float u0 = __expf(acc[mt][nt][0] * 0.125f);
                float u1 = __expf(acc[mt][nt][1] * 0.125f);
                float u2 = __expf(acc[mt][nt][2] * 0.125f);
                float u3 = __expf(acc[mt][nt][3] * 0.125f);
                zacc[mt][0] += u0 + u1;
                zacc[mt][1] += u2 + u3;
                *(__half2*)&Th[rl * P2S + cl]       = __floats2half2_rn(u0, u1);
                *(__half2*)&Th[(rl + 8) * P2S + cl] = __floats2half2_rn(u2, u3);
            }
        }
        if (kt < 15) cp_wait<1>();    // V(kt) done, K(kt+1) may fly
        else         cp_wait<0>();
        __syncthreads();

        // u-tile @ V^T -> acc1
#pragma unroll
        for (int kk = 0; kk < 8; kk++) {
            unsigned af[2][4];
            int c0 = kk * 16 + qid * 2;
#pragma unroll
            for (int mt = 0; mt < 2; mt++) {
                int r = wm * 32 + mt * 16 + grp;
                af[mt][0] = *(const unsigned*)&Th[r * P2S + c0];
                af[mt][1] = *(const unsigned*)&Th[(r + 8) * P2S + c0];
                af[mt][2] = *(const unsigned*)&Th[r * P2S + c0 + 8];
                af[mt][3] = *(const unsigned*)&Th[(r + 8) * P2S + c0 + 8];
            }
#pragma unroll
            for (int nt = 0; nt < 4; nt++) {
                int c = wn * 32 + nt * 8 + grp;
                unsigned b0 = *(const unsigned*)&Vh[c * P2S + c0];
                unsigned b1 = *(const unsigned*)&Vh[c * P2S + c0 + 8];
#pragma unroll
                for (int mt = 0; mt < 2; mt++)
                    mma16816(acc1[mt][nt], af[mt], b0, b1);
            }
        }
        __syncthreads();
    }

    // z reduction
#pragma unroll
    for (int mt = 0; mt < 2; mt++)
#pragma unroll
        for (int hf = 0; hf < 2; hf++) {
            float z = zacc[mt][hf];
            z += __shfl_xor_sync(0xffffffffu, z, 1);
            z += __shfl_xor_sync(0xffffffffu, z, 2);
            if (qid == 0) zbuf[wn * 128 + wm * 32 + mt * 16 + hf * 8 + grp] = z;
        }
    __syncthreads();
    if (tid < 128) sz[tid] = zbuf[tid] + zbuf[128 + tid];
    __syncthreads();

    // epilogue: out = (sumv + acc1/z) / 2049 -> fp16
    const float inv2049 = 1.0f / 2049.0f;
#pragma unroll
    for (int mt = 0; mt < 2; mt++) {
        int rl0 = wm * 32 + mt * 16 + grp;
        float iz0 = 1.0f / sz[rl0];
        float iz1 = 1.0f / sz[rl0 + 8];
#pragma unroll
        for (int nt = 0; nt < 4; nt++) {
            int dcol = wn * 32 + nt * 8 + qid * 2;
            float sv0 = sumv[bh * DK + dcol];
            float sv1 = sumv[bh * DK + dcol + 1];
            int c = h * DK + dcol;
            size_t o0 = ((size_t)(b * S_ + q0 + rl0)) * D_ + c;
            size_t o1 = ((size_t)(b * S_ + q0 + rl0 + 8)) * D_ + c;
            *(__half2*)&aout[o0] = __floats2half2_rn((sv0 + acc1[mt][nt][0] * iz0) * inv2049,
                                                     (sv1 + acc1[mt][nt][1] * iz0) * inv2049);
            *(__half2*)&aout[o1] = __floats2half2_rn((sv0 + acc1[mt][nt][2] * iz1) * inv2049,
                                                     (sv1 + acc1[mt][nt][3] * iz1) * inv2049);
        }
    }
}

// ---------------- launch ----------------
extern "C" void kernel_launch(void* const* d_in, const int* in_sizes, int n_in,
                              void* d_out, int out_size) {
    const float* x  = (const float*)d_in[0];
    const float* fc = (const float*)d_in[1];
    const float* fs = (const float*)d_in[2];
    const float* W[4] = {(const float*)d_in[3], (const float*)d_in[4],
                         (const float*)d_in[5], (const float*)d_in[6]};
    float* out = (float*)d_out;

    float *v, *sumvp;
    __half *xh, *ah, *wt, *qh, *kh, *vth;
    cudaGetSymbolAddress((void**)&v, g_v);
    cudaGetSymbolAddress((void**)&sumvp, g_sumv);
    cudaGetSymbolAddress((void**)&xh, g_xh);
    cudaGetSymbolAddress((void**)&ah, g_ah);
    cudaGetSymbolAddress((void**)&wt, g_wt);
    cudaGetSymbolAddress((void**)&qh, g_qh);
    cudaGetSymbolAddress((void**)&kh, g_kh);
    cudaGetSymbolAddress((void**)&vth, g_vth);

    cudaFuncSetAttribute(gemm_f16, cudaFuncAttributeMaxDynamicSharedMemorySize, G1SMEM);
    cudaFuncSetAttribute(gemm_rope2, cudaFuncAttributeMaxDynamicSharedMemorySize, G1SMEM);
    cudaFuncSetAttribute(attn_fused, cudaFuncAttributeMaxDynamicSharedMemorySize, FASMEM);

    convX<<<(MS_ * D_) / 256, 256>>>(x, xh);
    convWT4<<<dim3(32, 32, 4), 256>>>(W[0], W[1], W[2], W[3], wt);

    dim3 ggrid(8, 32);
    gemm_rope2<<<dim3(8, 32, 2), 256, G1SMEM>>>(xh, wt, fc, fs, qh, kh);
    gemm_f16<<<ggrid, 256, G1SMEM>>>(xh, wt + 2 * (size_t)D_ * D_, v);

    vtrans<<<dim3(S_ / 32, DK / 32, BH_), 256>>>(v, vth);
    sumv_kernel<<<BH_, 256>>>(v, sumvp);

    attn_fused<<<dim3(S_ / 128, BH_), 256, FASMEM>>>(qh, kh, vth, sumvp, ah);

    gemm_f16<<<ggrid, 256, G1SMEM>>>(ah, wt + 3 * (size_t)D_ * D_, out);
}

// round 16
// speedup vs baseline: 1.3065x; 1.0561x over previous
#include <cuda_runtime.h>
#include <cuda_bf16.h>
#include <cuda_fp16.h>
#include <math.h>

#define B_  2
#define S_  2048
#define D_  1024
#define H_  16
#define DK  64
#define BH_ (B_*H_)
#define MS_ (B_*S_)          // 4096 rows

// ---------------- scratch (static device arrays; no cudaMalloc) ----------------
__device__ float g_v[(size_t)MS_*D_];
__device__ float g_sumv[BH_*DK];
__device__ float g_svp[64 * BH_ * DK];           // partial v-sums per 32-row block
__device__ __half g_xh[(size_t)MS_*D_];          // x fp16
__device__ __half g_ah[(size_t)MS_*D_];          // attn fp16
__device__ __half g_wt[4][(size_t)D_*D_];        // W^T fp16 ([n][k])
__device__ __half g_qh[(size_t)MS_*D_];          // roped q fp16
__device__ __half g_kh[(size_t)MS_*D_];          // roped k fp16
__device__ __half g_vth[(size_t)BH_*DK*S_];      // V^T fp16 [b*h][dk][s]

// ================= helpers =================
__device__ __forceinline__ unsigned smem_u32(const void* p) {
    unsigned a;
    asm("{ .reg .u64 t; cvta.to.shared.u64 t, %1; cvt.u32.u64 %0, t; }" : "=r"(a) : "l"(p));
    return a;
}
__device__ __forceinline__ void cp16(unsigned saddr, const void* gaddr) {
    asm volatile("cp.async.cg.shared.global [%0], [%1], 16;" :: "r"(saddr), "l"(gaddr));
}
__device__ __forceinline__ void cp_commit() { asm volatile("cp.async.commit_group;"); }
template <int N>
__device__ __forceinline__ void cp_wait() { asm volatile("cp.async.wait_group %0;" :: "n"(N)); }

__device__ __forceinline__ void mma16816(float* c, const unsigned* a, unsigned b0, unsigned b1) {
    asm volatile("mma.sync.aligned.m16n8k16.row.col.f32.f16.f16.f32 "
                 "{%0,%1,%2,%3}, {%4,%5,%6,%7}, {%8,%9}, {%0,%1,%2,%3};"
                 : "+f"(c[0]), "+f"(c[1]), "+f"(c[2]), "+f"(c[3])
                 : "r"(a[0]), "r"(a[1]), "r"(a[2]), "r"(a[3]), "r"(b0), "r"(b1));
}

// ================= convert / transform kernels =================
__global__ void convX(const float* __restrict__ X, __half* __restrict__ out) {
    int i = blockIdx.x * 256 + threadIdx.x;
    out[i] = __float2half(X[i]);
}

// batched: W[z][k][n] -> WT fp16 [z][n][k]
__global__ void convWT4(const float* __restrict__ W0, const float* __restrict__ W1,
                        const float* __restrict__ W2, const float* __restrict__ W3,
                        __half* __restrict__ wt) {
    __shared__ float t[32][33];
    const float* Ws[4] = {W0, W1, W2, W3};
    const float* W = Ws[blockIdx.z];
    __half* dst = wt + (size_t)blockIdx.z * D_ * D_;
    int bx = blockIdx.x * 32, by = blockIdx.y * 32;
    int tx = threadIdx.x & 31, ty = threadIdx.x >> 5;
#pragma unroll
    for (int i = 0; i < 32; i += 8)
        t[ty + i][tx] = W[(size_t)(by + ty + i) * 1024 + bx + tx];
    __syncthreads();
#pragma unroll
    for (int i = 0; i < 32; i += 8)
        dst[(size_t)(bx + ty + i) * 1024 + by + tx] = __float2half(t[tx][ty + i]);
}

// V transpose + per-block partial sums (single read of v)
__global__ void vtrans_ps(const float* __restrict__ v, __half* __restrict__ vth,
                          float* __restrict__ svp) {
    __shared__ float t[32][33];
    int s0 = blockIdx.x * 32, d0 = blockIdx.y * 32;
    int bh = blockIdx.z, b = bh >> 4, h = bh & 15;
    int tx = threadIdx.x & 31, ty = threadIdx.x >> 5;
#pragma unroll
    for (int i = 0; i < 32; i += 8)
        t[ty + i][tx] = v[((size_t)(b * S_ + s0 + ty + i)) * D_ + h * DK + d0 + tx];
    __syncthreads();
#pragma unroll
    for (int i = 0; i < 32; i += 8)
        vth[((size_t)bh * DK + d0 + ty + i) * S_ + s0 + tx] = __float2half(t[tx][ty + i]);
    if (ty == 0) {
        float s = 0.f;
#pragma unroll
        for (int i = 0; i < 32; i++) s += t[i][tx];
        svp[(size_t)(s0 >> 5) * (BH_ * DK) + bh * DK + d0 + tx] = s;
    }
}

// final reduction: sumv[bh*DK+d] = sum over 64 s-blocks (deterministic order)
__global__ void sumv_final(const float* __restrict__ svp, float* __restrict__ sumv) {
    int i = blockIdx.x * 256 + threadIdx.x;   // 0..2047
    float s = 0.f;
    for (int k = 0; k < 64; k++) s += svp[(size_t)k * (BH_ * DK) + i];
    sumv[i] = s;
}

// ================= 1-term fp16 GEMM (K-chunk 32, double buffered) =================
#define SA    40
#define TILEB (128 * SA * 2)
#define B1B   (2 * TILEB)
#define G1SMEM (2 * B1B)

#define GEMM_MAINLOOP(ACCUM)                                                        \
    {                                                                               \
        _Pragma("unroll")                                                           \
        for (int t = 0; t < 2; t++)                                                 \
            _Pragma("unroll")                                                       \
            for (int u = 0; u < 2; u++) {                                           \
                int idx = tid * 2 + u;                                              \
                int row = idx >> 2, seg = idx & 3;                                  \
                cp16(sb + t * TILEB + row * 80 + seg * 16,                          \
                     srcs[t] + (size_t)(r0s[t] + row) * 1024 + seg * 8);            \
            }                                                                       \
        cp_commit();                                                                \
    }                                                                               \
    for (int ch = 0; ch < 32; ch++) {                                               \
        const int buf = ch & 1;                                                     \
        if (ch < 31) {                                                              \
            const int k0 = (ch + 1) * 32, nbuf = (ch + 1) & 1;                      \
            _Pragma("unroll")                                                       \
            for (int t = 0; t < 2; t++)                                             \
                _Pragma("unroll")                                                   \
                for (int u = 0; u < 2; u++) {                                       \
                    int idx = tid * 2 + u;                                          \
                    int row = idx >> 2, seg = idx & 3;                              \
                    cp16(sb + nbuf * B1B + t * TILEB + row * 80 + seg * 16,         \
                         srcs[t] + (size_t)(r0s[t] + row) * 1024 + k0 + seg * 8);   \
                }                                                                   \
            cp_commit();                                                            \
            cp_wait<1>();                                                           \
        } else {                                                                    \
            cp_wait<0>();                                                           \
        }                                                                           \
        __syncthreads();                                                            \
        const __half* Ah = (const __half*)(smc + buf * B1B);                        \
        const __half* Bh = Ah + 128 * SA;                                           \
        _Pragma("unroll")                                                           \
        for (int kk = 0; kk < 32; kk += 16) {                                       \
            unsigned af[2][4];                                                      \
            _Pragma("unroll")                                                       \
            for (int mt = 0; mt < 2; mt++) {                                        \
                int r = wm * 32 + mt * 16 + grp;                                    \
                af[mt][0] = *(const unsigned*)&Ah[r * SA + kk + qid * 2];           \
                af[mt][1] = *(const unsigned*)&Ah[(r + 8) * SA + kk + qid * 2];     \
                af[mt][2] = *(const unsigned*)&Ah[r * SA + kk + 8 + qid * 2];       \
                af[mt][3] = *(const unsigned*)&Ah[(r + 8) * SA + kk + 8 + qid * 2]; \
            }                                                                       \
            _Pragma("unroll")                                                       \
            for (int nt = 0; nt < 8; nt++) {                                        \
                int c = wn * 64 + nt * 8 + grp;                                     \
                unsigned b0 = *(const unsigned*)&Bh[c * SA + kk + qid * 2];         \
                unsigned b1 = *(const unsigned*)&Bh[c * SA + kk + 8 + qid * 2];     \
                _Pragma("unroll")                                                   \
                for (int mt = 0; mt < 2; mt++)                                      \
                    mma16816(ACCUM[mt][nt], af[mt], b0, b1);                        \
            }                                                                       \
        }                                                                           \
        __syncthreads();                                                            \
    }

// batched QKV projection: z=0 -> q(rope), z=1 -> k(rope), z=2 -> v(fp32)
__global__ __launch_bounds__(256, 2) void gemm_qkv(const __half* __restrict__ Ah_,
                                                   const __half* __restrict__ wt,
                                                   const float* __restrict__ fc,
                                                   const float* __restrict__ fs,
                                                   __half* __restrict__ qdst,
                                                   __half* __restrict__ kdst,
                                                   float* __restrict__ vdst) {
    extern __shared__ char smc[];
    const int tid = threadIdx.x, lane = tid & 31, wid = tid >> 5;
    const int wm = wid & 3, wn = wid >> 2;
    const int grp = lane >> 2, qid = lane & 3;
    const int m0 = blockIdx.y * 128, n0 = blockIdx.x * 128;
    const int z = blockIdx.z;
    const unsigned sb = smem_u32(smc);

    const __half* Bh_ = wt + (size_t)z * D_ * D_;
    const __half* srcs[2] = {Ah_, Bh_};
    const int r0s[2] = {m0, n0};

    float acc[2][8][4];
#pragma unroll
    for (int mt = 0; mt < 2; mt++)
#pragma unroll
        for (int nt = 0; nt < 8; nt++)
#pragma unroll
            for (int e = 0; e < 4; e++) acc[mt][nt][e] = 0.f;

    GEMM_MAINLOOP(acc)

    if (z == 2) {
#pragma unroll
        for (int mt = 0; mt < 2; mt++) {
            int r = m0 + wm * 32 + mt * 16 + grp;
#pragma unroll
            for (int nt = 0; nt < 8; nt++) {
                int c = n0 + wn * 64 + nt * 8 + qid * 2;
                *(float2*)&vdst[(size_t)r * 1024 + c]       = make_float2(acc[mt][nt][0], acc[mt][nt][1]);
                *(float2*)&vdst[(size_t)(r + 8) * 1024 + c] = make_float2(acc[mt][nt][2], acc[mt][nt][3]);
            }
        }
    } else {
        __half* dst = z ? kdst : qdst;
#pragma unroll
        for (int mt = 0; mt < 2; mt++) {
            int r = m0 + wm * 32 + mt * 16 + grp;
            int s = r & (S_ - 1);
#pragma unroll
            for (int nt = 0; nt < 8; nt++) {
                int c = n0 + wn * 64 + nt * 8 + qid * 2;
                int ii = (c & 63) >> 1;
                float c0 = fc[s * 32 + ii],       s0 = fs[s * 32 + ii];
                float c1 = fc[(s + 8) * 32 + ii], s1 = fs[(s + 8) * 32 + ii];
                float re0 = acc[mt][nt][0], im0 = acc[mt][nt][1];
                float re1 = acc[mt][nt][2], im1 = acc[mt][nt][3];
                __half2 p0, p1;
                p0.x = __float2half(re0 * c0 - im0 * s0);
                p0.y = __float2half(re0 * s0 + im0 * c0);
                p1.x = __float2half(re1 * c1 - im1 * s1);
                p1.y = __float2half(re1 * s1 + im1 * c1);
                *(__half2*)&dst[(size_t)r * 1024 + c]       = p0;
                *(__half2*)&dst[(size_t)(r + 8) * 1024 + c] = p1;
            }
        }
    }
}

// plain GEMM for Wo
__global__ __launch_bounds__(256, 2) void gemm_f16(const __half* __restrict__ Ah_,
                                                   const __half* __restrict__ Bh_,
                                                   float* __restrict__ C) {
    extern __shared__ char smc[];
    const int tid = threadIdx.x, lane = tid & 31, wid = tid >> 5;
    const int wm = wid & 3, wn = wid >> 2;
    const int grp = lane >> 2, qid = lane & 3;
    const int m0 = blockIdx.y * 128, n0 = blockIdx.x * 128;
    const unsigned sb = smem_u32(smc);

    const __half* srcs[2] = {Ah_, Bh_};
    const int r0s[2] = {m0, n0};

    float acc[2][8][4];
#pragma unroll
    for (int mt = 0; mt < 2; mt++)
#pragma unroll
        for (int nt = 0; nt < 8; nt++)
#pragma unroll
            for (int e = 0; e < 4; e++) acc[mt][nt][e] = 0.f;

    GEMM_MAINLOOP(acc)

#pragma unroll
    for (int mt = 0; mt < 2; mt++) {
        int r = m0 + wm * 32 + mt * 16 + grp;
#pragma unroll
        for (int nt = 0; nt < 8; nt++) {
            int c = n0 + wn * 64 + nt * 8 + qid * 2;
            *(float2*)&C[(size_t)r * 1024 + c]       = make_float2(acc[mt][nt][0], acc[mt][nt][1]);
            *(float2*)&C[(size_t)(r + 8) * 1024 + c] = make_float2(acc[mt][nt][2], acc[mt][nt][3]);
        }
    }
}

// ================= single-pass fused attention (no score buffer) =================
// out = (sumv + (U@V)/z) / 2049; V double-buffered (buf0 reuses the Q region)
#define P1S   72
#define P1ROW (P1S * 2)       // 144
#define P1T   (128 * P1ROW)   // 18432
#define P2S   136
#define P2ROW (P2S * 2)       // 272
#define ATT_TH (3 * P1T)               // 55296
#define ATT_V1 (ATT_TH + 128 * P2ROW)  // 90112  (V buffer 1; buffer 0 at offset 0)
#define ATT_ZB (ATT_V1 + 64 * P2ROW)   // 107520
#define ATT_SZ (ATT_ZB + 1024)         // 108544
#define FASMEM (ATT_SZ + 512)          // 109056

__global__ __launch_bounds__(256, 2) void attn_fused(const __half* __restrict__ qh,
                                                     const __half* __restrict__ kh,
                                                     const __half* __restrict__ vth,
                                                     const float* __restrict__ sumv,
                                                     __half* __restrict__ aout) {
    extern __shared__ char smc[];
    const unsigned sb = smem_u32(smc);
    const int tid = threadIdx.x, lane = tid & 31, wid = tid >> 5;
    const int wm = wid & 3, wn = wid >> 2;
    const int grp = lane >> 2, qid = lane & 3;
    const int bh = blockIdx.y, b = bh >> 4, h = bh & 15;
    const int q0 = blockIdx.x * 128;
    float* zbuf = (float*)(smc + ATT_ZB);
    float* sz   = (float*)(smc + ATT_SZ);
    __half* Th = (__half*)(smc + ATT_TH);

    // prologue: Q tile + K tile 0 (one group)
    {
#pragma unroll
        for (int u = 0; u < 4; u++) {
            int idx = tid * 4 + u;
            int row = idx >> 3, ch = idx & 7;
            cp16(sb + row * P1ROW + ch * 16,
                 qh + ((size_t)(b * S_ + q0 + row)) * D_ + h * DK + ch * 8);
        }
#pragma unroll
        for (int u = 0; u < 4; u++) {
            int idx = tid * 4 + u;
            int row = idx >> 3, ch = idx & 7;
            cp16(sb + P1T + row * P1ROW + ch * 16,
                 kh + ((size_t)(b * S_ + row)) * D_ + h * DK + ch * 8);
        }
        cp_commit();
    }
    cp_wait<0>();
    __syncthreads();

    unsigned qf[2][4][4];
    {
        const __half* Qh = (const __half*)smc;
#pragma unroll
        for (int mt = 0; mt < 2; mt++) {
            int r = wm * 32 + mt * 16 + grp;
#pragma unroll
            for (int kk = 0; kk < 4; kk++) {
                int c0 = kk * 16 + qid * 2;
                qf[mt][kk][0] = *(const unsigned*)&Qh[r * P1S + c0];
                qf[mt][kk][1] = *(const unsigned*)&Qh[(r + 8) * P1S + c0];
                qf[mt][kk][2] = *(const unsigned*)&Qh[r * P1S + c0 + 8];
                qf[mt][kk][3] = *(const unsigned*)&Qh[(r + 8) * P1S + c0 + 8];
            }
        }
    }
    __syncthreads();   // all Q reads done before V0 overwrites the Q region

    float zacc[2][2] = {{0.f, 0.f}, {0.f, 0.f}};
    float acc1[2][4][4];
#pragma unroll
    for (int mt = 0; mt < 2; mt++)
#pragma unroll
        for (int nt = 0; nt < 4; nt++)
#pragma unroll
            for (int e = 0; e < 4; e++) acc1[mt][nt][e] = 0.f;

    for (int kt = 0; kt < 16; kt++) {
        const int buf = kt & 1;
        const unsigned vbase = buf ? (sb + ATT_V1) : sb;     // V buffer (0 = Q region)
        // V(kt) load (own group)
        {
#pragma unroll
            for (int u = 0; u < 4; u++) {
                int idx = tid * 4 + u;
                int row = idx >> 4, ch = idx & 15;
                cp16(vbase + row * P2ROW + ch * 16,
                     vth + ((size_t)bh * DK + row) * S_ + kt * 128 + ch * 8);
            }
            cp_commit();
        }
        // K(kt+1) prefetch
        if (kt < 15) {
            const int nbuf = (kt + 1) & 1;
#pragma unroll
            for (int u = 0; u < 4; u++) {
                int idx = tid * 4 + u;
                int row = idx >> 3, ch = idx & 7;
                cp16(sb + (1 + nbuf) * P1T + row * P1ROW + ch * 16,
                     kh + ((size_t)(b * S_ + (kt + 1) * 128 + row)) * D_ + h * DK + ch * 8);
            }
            cp_commit();
            cp_wait<2>();     // K(kt) done
        } else {
            cp_wait<1>();     // K(15) done, V(15) in flight
        }
        __syncthreads();

        const __half* Kh = (const __half*)(smc + (1 + buf) * P1T);

        // s-tile = Q @ K^T
        float acc[2][8][4];
#pragma unroll
        for (int mt = 0; mt < 2; mt++)
#pragma unroll
            for (int nt = 0; nt < 8; nt++)
#pragma unroll
                for (int e = 0; e < 4; e++) acc[mt][nt][e] = 0.f;

#pragma unroll
        for (int kk = 0; kk < 4; kk++) {
#pragma unroll
            for (int nt = 0; nt < 8; nt++) {
                int c = wn * 64 + nt * 8 + grp;
                int c0 = kk * 16 + qid * 2;
                unsigned b0 = *(const unsigned*)&Kh[c * P1S + c0];
                unsigned b1 = *(const unsigned*)&Kh[c * P1S + c0 + 8];
#pragma unroll
                for (int mt = 0; mt < 2; mt++)
                    mma16816(acc[mt][nt], qf[mt][kk], b0, b1);
            }
        }

        // u = exp(s/8): z accumulate, store u tile -> smem
#pragma unroll
        for (int mt = 0; mt < 2; mt++) {
            int rl = wm * 32 + mt * 16 + grp;
#pragma unroll
            for (int nt = 0; nt < 8; nt++) {
                int cl = wn * 64 + nt * 8 + qid * 2;
                float u0 = __expf(acc[mt][nt][0] * 0.125f);
                float u1 = __expf(acc[mt][nt][1] * 0.125f);
                float u2 = __expf(acc[mt][nt][2] * 0.125f);
                float u3 = __expf(acc[mt][nt][3] * 0.125f);
                zacc[mt][0] += u0 + u1;
                zacc[mt][1] += u2 + u3;
                *(__half2*)&Th[rl * P2S + cl]       = __floats2half2_rn(u0, u1);
                *(__half2*)&Th[(rl + 8) * P2S + cl] = __floats2half2_rn(u2, u3);
            }
        }
        if (kt < 15) cp_wait<1>();    // V(kt) done, K(kt+1) may fly
        else         cp_wait<0>();
        __syncthreads();

        // u-tile @ V^T -> acc1
        const __half* Vh = (const __half*)(smc + (buf ? ATT_V1 : 0));
#pragma unroll
        for (int kk = 0; kk < 8; kk++) {
            unsigned af[2][4];
            int c0 = kk * 16 + qid * 2;
#pragma unroll
            for (int mt = 0; mt < 2; mt++) {
                int r = wm * 32 + mt * 16 + grp;
                af[mt][0] = *(const unsigned*)&Th[r * P2S + c0];
                af[mt][1] = *(const unsigned*)&Th[(r + 8) * P2S + c0];
                af[mt][2] = *(const unsigned*)&Th[r * P2S + c0 + 8];
                af[mt][3] = *(const unsigned*)&Th[(r + 8) * P2S + c0 + 8];
            }
#pragma unroll
            for (int nt = 0; nt < 4; nt++) {
                int c = wn * 32 + nt * 8 + grp;
                unsigned b0 = *(const unsigned*)&Vh[c * P2S + c0];
                unsigned b1 = *(const unsigned*)&Vh[c * P2S + c0 + 8];
#pragma unroll
                for (int mt = 0; mt < 2; mt++)
                    mma16816(acc1[mt][nt], af[mt], b0, b1);
            }
        }
        // no loop-end sync: V double-buffered; Th protected by next sync1
    }

    // z reduction
#pragma unroll
    for (int mt = 0; mt < 2; mt++)
#pragma unroll
        for (int hf = 0; hf < 2; hf++) {
            float z = zacc[mt][hf];
            z += __shfl_xor_sync(0xffffffffu, z, 1);
            z += __shfl_xor_sync(0xffffffffu, z, 2);
            if (qid == 0) zbuf[wn * 128 + wm * 32 + mt * 16 + hf * 8 + grp] = z;
        }
    __syncthreads();
    if (tid < 128) sz[tid] = zbuf[tid] + zbuf[128 + tid];
    __syncthreads();

    // epilogue: out = (sumv + acc1/z) / 2049 -> fp16
    const float inv2049 = 1.0f / 2049.0f;
#pragma unroll
    for (int mt = 0; mt < 2; mt++) {
        int rl0 = wm * 32 + mt * 16 + grp;
        float iz0 = 1.0f / sz[rl0];
        float iz1 = 1.0f / sz[rl0 + 8];
#pragma unroll
        for (int nt = 0; nt < 4; nt++) {
            int dcol = wn * 32 + nt * 8 + qid * 2;
            float sv0 = sumv[bh * DK + dcol];
            float sv1 = sumv[bh * DK + dcol + 1];
            int c = h * DK + dcol;
            size_t o0 = ((size_t)(b * S_ + q0 + rl0)) * D_ + c;
            size_t o1 = ((size_t)(b * S_ + q0 + rl0 + 8)) * D_ + c;
            *(__half2*)&aout[o0] = __floats2half2_rn((sv0 + acc1[mt][nt][0] * iz0) * inv2049,
                                                     (sv1 + acc1[mt][nt][1] * iz0) * inv2049);
            *(__half2*)&aout[o1] = __floats2half2_rn((sv0 + acc1[mt][nt][2] * iz1) * inv2049,
                                                     (sv1 + acc1[mt][nt][3] * iz1) * inv2049);
        }
    }
}

// ---------------- launch ----------------
extern "C" void kernel_launch(void* const* d_in, const int* in_sizes, int n_in,
                              void* d_out, int out_size) {
    const float* x  = (const float*)d_in[0];
    const float* fc = (const float*)d_in[1];
    const float* fs = (const float*)d_in[2];
    const float* W[4] = {(const float*)d_in[3], (const float*)d_in[4],
                         (const float*)d_in[5], (const float*)d_in[6]};
    float* out = (float*)d_out;

    float *v, *sumvp, *svp;
    __half *xh, *ah, *wt, *qh, *kh, *vth;
    cudaGetSymbolAddress((void**)&v, g_v);
    cudaGetSymbolAddress((void**)&sumvp, g_sumv);
    cudaGetSymbolAddress((void**)&svp, g_svp);
    cudaGetSymbolAddress((void**)&xh, g_xh);
    cudaGetSymbolAddress((void**)&ah, g_ah);
    cudaGetSymbolAddress((void**)&wt, g_wt);
    cudaGetSymbolAddress((void**)&qh, g_qh);
    cudaGetSymbolAddress((void**)&kh, g_kh);
    cudaGetSymbolAddress((void**)&vth, g_vth);

    cudaFuncSetAttribute(gemm_qkv, cudaFuncAttributeMaxDynamicSharedMemorySize, G1SMEM);
    cudaFuncSetAttribute(gemm_f16, cudaFuncAttributeMaxDynamicSharedMemorySize, G1SMEM);
    cudaFuncSetAttribute(attn_fused, cudaFuncAttributeMaxDynamicSharedMemorySize, FASMEM);

    convX<<<(MS_ * D_) / 256, 256>>>(x, xh);
    convWT4<<<dim3(32, 32, 4), 256>>>(W[0], W[1], W[2], W[3], wt);

    gemm_qkv<<<dim3(8, 32, 3), 256, G1SMEM>>>(xh, wt, fc, fs, qh, kh, v);

    vtrans_ps<<<dim3(S_ / 32, DK / 32, BH_), 256>>>(v, vth, svp);
    sumv_final<<<8, 256>>>(svp, sumvp);

    attn_fused<<<dim3(S_ / 128, BH_), 256, FASMEM>>>(qh, kh, vth, sumvp, ah);

    gemm_f16<<<dim3(8, 32), 256, G1SMEM>>>(ah, wt + 3 * (size_t)D_ * D_, out);
}

// round 17
// speedup vs baseline: 1.3548x; 1.0370x over previous
#include <cuda_runtime.h>
#include <cuda_bf16.h>
#include <cuda_fp16.h>
#include <math.h>

#define B_  2
#define S_  2048
#define D_  1024
#define H_  16
#define DK  64
#define BH_ (B_*H_)
#define MS_ (B_*S_)          // 4096 rows

// ---------------- scratch (static device arrays; no cudaMalloc) ----------------
__device__ float g_v[(size_t)MS_*D_];
__device__ float g_sumv[BH_*DK];
__device__ float g_svp[64 * BH_ * DK];           // partial v-sums per 32-row block
__device__ __half g_xh[(size_t)MS_*D_];          // x fp16
__device__ __half g_ah[(size_t)MS_*D_];          // attn fp16
__device__ __half g_wt[4][(size_t)D_*D_];        // W^T fp16 ([n][k])
__device__ __half g_qh[(size_t)MS_*D_];          // roped q fp16
__device__ __half g_kh[(size_t)MS_*D_];          // roped k fp16
__device__ __half g_vth[(size_t)BH_*DK*S_];      // V^T fp16 [b*h][dk][s]

// ================= helpers =================
__device__ __forceinline__ unsigned smem_u32(const void* p) {
    unsigned a;
    asm("{ .reg .u64 t; cvta.to.shared.u64 t, %1; cvt.u32.u64 %0, t; }" : "=r"(a) : "l"(p));
    return a;
}
__device__ __forceinline__ void cp16(unsigned saddr, const void* gaddr) {
    asm volatile("cp.async.cg.shared.global [%0], [%1], 16;" :: "r"(saddr), "l"(gaddr));
}
__device__ __forceinline__ void cp_commit() { asm volatile("cp.async.commit_group;"); }
template <int N>
__device__ __forceinline__ void cp_wait() { asm volatile("cp.async.wait_group %0;" :: "n"(N)); }

__device__ __forceinline__ void mma16816(float* c, const unsigned* a, unsigned b0, unsigned b1) {
    asm volatile("mma.sync.aligned.m16n8k16.row.col.f32.f16.f16.f32 "
                 "{%0,%1,%2,%3}, {%4,%5,%6,%7}, {%8,%9}, {%0,%1,%2,%3};"
                 : "+f"(c[0]), "+f"(c[1]), "+f"(c[2]), "+f"(c[3])
                 : "r"(a[0]), "r"(a[1]), "r"(a[2]), "r"(a[3]), "r"(b0), "r"(b1));
}
__device__ __forceinline__ unsigned ph2(float lo, float hi) {
    __half2 t = __floats2half2_rn(lo, hi);
    return *(unsigned*)&t;
}

// ================= convert / transform kernels =================
__global__ void convX(const float* __restrict__ X, __half* __restrict__ out) {
    int i = blockIdx.x * 256 + threadIdx.x;
    out[i] = __float2half(X[i]);
}

// batched: W[z][k][n] -> WT fp16 [z][n][k]
__global__ void convWT4(const float* __restrict__ W0, const float* __restrict__ W1,
                        const float* __restrict__ W2, const float* __restrict__ W3,
                        __half* __restrict__ wt) {
    __shared__ float t[32][33];
    const float* Ws[4] = {W0, W1, W2, W3};
    const float* W = Ws[blockIdx.z];
    __half* dst = wt + (size_t)blockIdx.z * D_ * D_;
    int bx = blockIdx.x * 32, by = blockIdx.y * 32;
    int tx = threadIdx.x & 31, ty = threadIdx.x >> 5;
#pragma unroll
    for (int i = 0; i < 32; i += 8)
        t[ty + i][tx] = W[(size_t)(by + ty + i) * 1024 + bx + tx];
    __syncthreads();
#pragma unroll
    for (int i = 0; i < 32; i += 8)
        dst[(size_t)(bx + ty + i) * 1024 + by + tx] = __float2half(t[tx][ty + i]);
}

// V transpose + per-block partial sums (single read of v)
__global__ void vtrans_ps(const float* __restrict__ v, __half* __restrict__ vth,
                          float* __restrict__ svp) {
    __shared__ float t[32][33];
    int s0 = blockIdx.x * 32, d0 = blockIdx.y * 32;
    int bh = blockIdx.z, b = bh >> 4, h = bh & 15;
    int tx = threadIdx.x & 31, ty = threadIdx.x >> 5;
#pragma unroll
    for (int i = 0; i < 32; i += 8)
        t[ty + i][tx] = v[((size_t)(b * S_ + s0 + ty + i)) * D_ + h * DK + d0 + tx];
    __syncthreads();
#pragma unroll
    for (int i = 0; i < 32; i += 8)
        vth[((size_t)bh * DK + d0 + ty + i) * S_ + s0 + tx] = __float2half(t[tx][ty + i]);
    if (ty == 0) {
        float s = 0.f;
#pragma unroll
        for (int i = 0; i < 32; i++) s += t[i][tx];
        svp[(size_t)(s0 >> 5) * (BH_ * DK) + bh * DK + d0 + tx] = s;
    }
}

// final reduction (deterministic order)
__global__ void sumv_final(const float* __restrict__ svp, float* __restrict__ sumv) {
    int i = blockIdx.x * 256 + threadIdx.x;
    float s = 0.f;
    for (int k = 0; k < 64; k++) s += svp[(size_t)k * (BH_ * DK) + i];
    sumv[i] = s;
}

// ================= 1-term fp16 GEMM (K-chunk 32, double buffered) =================
#define SA    40
#define TILEB (128 * SA * 2)
#define B1B   (2 * TILEB)
#define G1SMEM (2 * B1B)

#define GEMM_MAINLOOP(ACCUM)                                                        \
    {                                                                               \
        _Pragma("unroll")                                                           \
        for (int t = 0; t < 2; t++)                                                 \
            _Pragma("unroll")                                                       \
            for (int u = 0; u < 2; u++) {                                           \
                int idx = tid * 2 + u;                                              \
                int row = idx >> 2, seg = idx & 3;                                  \
                cp16(sb + t * TILEB + row * 80 + seg * 16,                          \
                     srcs[t] + (size_t)(r0s[t] + row) * 1024 + seg * 8);            \
            }                                                                       \
        cp_commit();                                                                \
    }                                                                               \
    for (int ch = 0; ch < 32; ch++) {                                               \
        const int buf = ch & 1;                                                     \
        if (ch < 31) {                                                              \
            const int k0 = (ch + 1) * 32, nbuf = (ch + 1) & 1;                      \
            _Pragma("unroll")                                                       \
            for (int t = 0; t < 2; t++)                                             \
                _Pragma("unroll")                                                   \
                for (int u = 0; u < 2; u++) {                                       \
                    int idx = tid * 2 + u;                                          \
                    int row = idx >> 2, seg = idx & 3;                              \
                    cp16(sb + nbuf * B1B + t * TILEB + row * 80 + seg * 16,         \
                         srcs[t] + (size_t)(r0s[t] + row) * 1024 + k0 + seg * 8);   \
                }                                                                   \
            cp_commit();                                                            \
            cp_wait<1>();                                                           \
        } else {                                                                    \
            cp_wait<0>();                                                           \
        }                                                                           \
        __syncthreads();                                                            \
        const __half* Ah = (const __half*)(smc + buf * B1B);                        \
        const __half* Bh = Ah + 128 * SA;                                           \
        _Pragma("unroll")                                                           \
        for (int kk = 0; kk < 32; kk += 16) {                                       \
            unsigned af[2][4];                                                      \
            _Pragma("unroll")                                                       \
            for (int mt = 0; mt < 2; mt++) {                                        \
                int r = wm * 32 + mt * 16 + grp;                                    \
                af[mt][0] = *(const unsigned*)&Ah[r * SA + kk + qid * 2];           \
                af[mt][1] = *(const unsigned*)&Ah[(r + 8) * SA + kk + qid * 2];     \
                af[mt][2] = *(const unsigned*)&Ah[r * SA + kk + 8 + qid * 2];       \
                af[mt][3] = *(const unsigned*)&Ah[(r + 8) * SA + kk + 8 + qid * 2]; \
            }                                                                       \
            _Pragma("unroll")                                                       \
            for (int nt = 0; nt < 8; nt++) {                                        \
                int c = wn * 64 + nt * 8 + grp;                                     \
                unsigned b0 = *(const unsigned*)&Bh[c * SA + kk + qid * 2];         \
                unsigned b1 = *(const unsigned*)&Bh[c * SA + kk + 8 + qid * 2];     \
                _Pragma("unroll")                                                   \
                for (int mt = 0; mt < 2; mt++)                                      \
                    mma16816(ACCUM[mt][nt], af[mt], b0, b1);                        \
            }                                                                       \
        }                                                                           \
        __syncthreads();                                                            \
    }

// batched QKV projection: z=0 -> q(rope), z=1 -> k(rope), z=2 -> v(fp32)
__global__ __launch_bounds__(256, 2) void gemm_qkv(const __half* __restrict__ Ah_,
                                                   const __half* __restrict__ wt,
                                                   const float* __restrict__ fc,
                                                   const float* __restrict__ fs,
                                                   __half* __restrict__ qdst,
                                                   __half* __restrict__ kdst,
                                                   float* __restrict__ vdst) {
    extern __shared__ char smc[];
    const int tid = threadIdx.x, lane = tid & 31, wid = tid >> 5;
    const int wm = wid & 3, wn = wid >> 2;
    const int grp = lane >> 2, qid = lane & 3;
    const int m0 = blockIdx.y * 128, n0 = blockIdx.x * 128;
    const int z = blockIdx.z;
    const unsigned sb = smem_u32(smc);

    const __half* Bh_ = wt + (size_t)z * D_ * D_;
    const __half* srcs[2] = {Ah_, Bh_};
    const int r0s[2] = {m0, n0};

    float acc[2][8][4];
#pragma unroll
    for (int mt = 0; mt < 2; mt++)
#pragma unroll
        for (int nt = 0; nt < 8; nt++)
#pragma unroll
            for (int e = 0; e < 4; e++) acc[mt][nt][e] = 0.f;

    GEMM_MAINLOOP(acc)

    if (z == 2) {
#pragma unroll
        for (int mt = 0; mt < 2; mt++) {
            int r = m0 + wm * 32 + mt * 16 + grp;
#pragma unroll
            for (int nt = 0; nt < 8; nt++) {
                int c = n0 + wn * 64 + nt * 8 + qid * 2;
                *(float2*)&vdst[(size_t)r * 1024 + c]       = make_float2(acc[mt][nt][0], acc[mt][nt][1]);
                *(float2*)&vdst[(size_t)(r + 8) * 1024 + c] = make_float2(acc[mt][nt][2], acc[mt][nt][3]);
            }
        }
    } else {
        __half* dst = z ? kdst : qdst;
#pragma unroll
        for (int mt = 0; mt < 2; mt++) {
            int r = m0 + wm * 32 + mt * 16 + grp;
            int s = r & (S_ - 1);
#pragma unroll
            for (int nt = 0; nt < 8; nt++) {
                int c = n0 + wn * 64 + nt * 8 + qid * 2;
                int ii = (c & 63) >> 1;
                float c0 = fc[s * 32 + ii],       s0 = fs[s * 32 + ii];
                float c1 = fc[(s + 8) * 32 + ii], s1 = fs[(s + 8) * 32 + ii];
                float re0 = acc[mt][nt][0], im0 = acc[mt][nt][1];
                float re1 = acc[mt][nt][2], im1 = acc[mt][nt][3];
                __half2 p0, p1;
                p0.x = __float2half(re0 * c0 - im0 * s0);
                p0.y = __float2half(re0 * s0 + im0 * c0);
                p1.x = __float2half(re1 * c1 - im1 * s1);
                p1.y = __float2half(re1 * s1 + im1 * c1);
                *(__half2*)&dst[(size_t)r * 1024 + c]       = p0;
                *(__half2*)&dst[(size_t)(r + 8) * 1024 + c] = p1;
            }
        }
    }
}

// plain GEMM for Wo
__global__ __launch_bounds__(256, 2) void gemm_f16(const __half* __restrict__ Ah_,
                                                   const __half* __restrict__ Bh_,
                                                   float* __restrict__ C) {
    extern __shared__ char smc[];
    const int tid = threadIdx.x, lane = tid & 31, wid = tid >> 5;
    const int wm = wid & 3, wn = wid >> 2;
    const int grp = lane >> 2, qid = lane & 3;
    const int m0 = blockIdx.y * 128, n0 = blockIdx.x * 128;
    const unsigned sb = smem_u32(smc);

    const __half* srcs[2] = {Ah_, Bh_};
    const int r0s[2] = {m0, n0};

    float acc[2][8][4];
#pragma unroll
    for (int mt = 0; mt < 2; mt++)
#pragma unroll
        for (int nt = 0; nt < 8; nt++)
#pragma unroll
            for (int e = 0; e < 4; e++) acc[mt][nt][e] = 0.f;

    GEMM_MAINLOOP(acc)

#pragma unroll
    for (int mt = 0; mt < 2; mt++) {
        int r = m0 + wm * 32 + mt * 16 + grp;
#pragma unroll
        for (int nt = 0; nt < 8; nt++) {
            int c = n0 + wn * 64 + nt * 8 + qid * 2;
            *(float2*)&C[(size_t)r * 1024 + c]       = make_float2(acc[mt][nt][0], acc[mt][nt][1]);
            *(float2*)&C[(size_t)(r + 8) * 1024 + c] = make_float2(acc[mt][nt][2], acc[mt][nt][3]);
        }
    }
}

// ================= single-pass attention, register-fragment u (no Th smem) =====
// out = (sumv + (U@V)/z) / 2049; warp wn handles k-cols [wn*64, wn*64+64)
#define P1S   72
#define P1ROW (P1S * 2)       // 144
#define P1T   (128 * P1ROW)   // 18432 (K tile / Q tile)
#define P2S   136
#define P2ROW (P2S * 2)       // 272
#define P2VT  (64 * P2ROW)    // 17408 (V tile)
#define KVBUF (P1T + P2VT)    // 35840 per stage: K @ +0, V @ +P1T
#define ATT_ZB (2 * KVBUF)    // 71680
#define ATT_SZ (ATT_ZB + 1024)
#define FASMEM (ATT_SZ + 512) // 73216
#define MRGS  66              // merge buffer row stride (floats)

__global__ __launch_bounds__(256, 2) void attn_fused(const __half* __restrict__ qh,
                                                     const __half* __restrict__ kh,
                                                     const __half* __restrict__ vth,
                                                     const float* __restrict__ sumv,
                                                     __half* __restrict__ aout) {
    extern __shared__ char smc[];
    const unsigned sb = smem_u32(smc);
    const int tid = threadIdx.x, lane = tid & 31, wid = tid >> 5;
    const int wm = wid & 3, wn = wid >> 2;
    const int grp = lane >> 2, qid = lane & 3;
    const int bh = blockIdx.y, b = bh >> 4, h = bh & 15;
    const int q0 = blockIdx.x * 128;
    float* zbuf = (float*)(smc + ATT_ZB);
    float* sz   = (float*)(smc + ATT_SZ);

    // prologue: Q tile into stage-0 K slot
    {
#pragma unroll
        for (int u = 0; u < 4; u++) {
            int idx = tid * 4 + u;
            int row = idx >> 3, ch = idx & 7;
            cp16(sb + row * P1ROW + ch * 16,
                 qh + ((size_t)(b * S_ + q0 + row)) * D_ + h * DK + ch * 8);
        }
        cp_commit();
    }
    cp_wait<0>();
    __syncthreads();

    unsigned qf[2][4][4];
    {
        const __half* Qh = (const __half*)smc;
#pragma unroll
        for (int mt = 0; mt < 2; mt++) {
            int r = wm * 32 + mt * 16 + grp;
#pragma unroll
            for (int kk = 0; kk < 4; kk++) {
                int c0 = kk * 16 + qid * 2;
                qf[mt][kk][0] = *(const unsigned*)&Qh[r * P1S + c0];
                qf[mt][kk][1] = *(const unsigned*)&Qh[(r + 8) * P1S + c0];
                qf[mt][kk][2] = *(const unsigned*)&Qh[r * P1S + c0 + 8];
                qf[mt][kk][3] = *(const unsigned*)&Qh[(r + 8) * P1S + c0 + 8];
            }
        }
    }
    __syncthreads();   // Q reads done before K0 overwrites the region

    // issue stage 0: K(0) + V(0) (one group)
    {
#pragma unroll
        for (int u = 0; u < 4; u++) {
            int idx = tid * 4 + u;
            int row = idx >> 3, ch = idx & 7;
            cp16(sb + row * P1ROW + ch * 16,
                 kh + ((size_t)(b * S_ + row)) * D_ + h * DK + ch * 8);
        }
#pragma unroll
        for (int u = 0; u < 4; u++) {
            int idx = tid * 4 + u;
            int row = idx >> 4, ch = idx & 15;
            cp16(sb + P1T + row * P2ROW + ch * 16,
                 vth + ((size_t)bh * DK + row) * S_ + ch * 8);
        }
        cp_commit();
    }

    float zacc[2][2] = {{0.f, 0.f}, {0.f, 0.f}};
    float acc1[2][8][4];
#pragma unroll
    for (int mt = 0; mt < 2; mt++)
#pragma unroll
        for (int nt = 0; nt < 8; nt++)
#pragma unroll
            for (int e = 0; e < 4; e++) acc1[mt][nt][e] = 0.f;

    for (int kt = 0; kt < 16; kt++) {
        cp_wait<0>();       // stage (kt) arrived
        __syncthreads();    // + all warps done with the other stage
        if (kt < 15) {
            const unsigned nb = sb + ((kt + 1) & 1) * KVBUF;
#pragma unroll
            for (int u = 0; u < 4; u++) {
                int idx = tid * 4 + u;
                int row = idx >> 3, ch = idx & 7;
                cp16(nb + row * P1ROW + ch * 16,
                     kh + ((size_t)(b * S_ + (kt + 1) * 128 + row)) * D_ + h * DK + ch * 8);
            }
#pragma unroll
            for (int u = 0; u < 4; u++) {
                int idx = tid * 4 + u;
                int row = idx >> 4, ch = idx & 15;
                cp16(nb + P1T + row * P2ROW + ch * 16,
                     vth + ((size_t)bh * DK + row) * S_ + (kt + 1) * 128 + ch * 8);
            }
            cp_commit();
        }

        const __half* Kh = (const __half*)(smc + (kt & 1) * KVBUF);
        const __half* Vh = (const __half*)(smc + (kt & 1) * KVBUF + P1T);
        const int kb0 = wn * 64;

#pragma unroll
        for (int g = 0; g < 4; g++) {
            // QK for u-tiles nt = 2g, 2g+1 (k-cols kb0 + g*16 .. +16)
            float accp[2][2][4];
#pragma unroll
            for (int mt = 0; mt < 2; mt++)
#pragma unroll
                for (int t = 0; t < 2; t++)
#pragma unroll
                    for (int e = 0; e < 4; e++) accp[mt][t][e] = 0.f;

#pragma unroll
            for (int kk = 0; kk < 4; kk++) {
#pragma unroll
                for (int t = 0; t < 2; t++) {
                    int c = kb0 + g * 16 + t * 8 + grp;
                    int c0 = kk * 16 + qid * 2;
                    unsigned b0 = *(const unsigned*)&Kh[c * P1S + c0];
                    unsigned b1 = *(const unsigned*)&Kh[c * P1S + c0 + 8];
#pragma unroll
                    for (int mt = 0; mt < 2; mt++)
                        mma16816(accp[mt][t], qf[mt][kk], b0, b1);
                }
            }

            // u = exp(s/8) in regs; z accumulate; pack A fragments
            unsigned ap[2][4];
#pragma unroll
            for (int mt = 0; mt < 2; mt++) {
                float u00 = __expf(accp[mt][0][0] * 0.125f);
                float u01 = __expf(accp[mt][0][1] * 0.125f);
                float u02 = __expf(accp[mt][0][2] * 0.125f);
                float u03 = __expf(accp[mt][0][3] * 0.125f);
                float u10 = __expf(accp[mt][1][0] * 0.125f);
                float u11 = __expf(accp[mt][1][1] * 0.125f);
                float u12 = __expf(accp[mt][1][2] * 0.125f);
                float u13 = __expf(accp[mt][1][3] * 0.125f);
                zacc[mt][0] += (u00 + u01) + (u10 + u11);
                zacc[mt][1] += (u02 + u03) + (u12 + u13);
                ap[mt][0] = ph2(u00, u01);
                ap[mt][1] = ph2(u02, u03);
                ap[mt][2] = ph2(u10, u11);
                ap[mt][3] = ph2(u12, u13);
            }

            // UV: k16 block at kb0 + g*16, all 64 d columns
            const int kb = kb0 + g * 16;
#pragma unroll
            for (int nt = 0; nt < 8; nt++) {
                int c = nt * 8 + grp;
                unsigned b0 = *(const unsigned*)&Vh[c * P2S + kb + qid * 2];
                unsigned b1 = *(const unsigned*)&Vh[c * P2S + kb + 8 + qid * 2];
#pragma unroll
                for (int mt = 0; mt < 2; mt++)
                    mma16816(acc1[mt][nt], ap[mt], b0, b1);
            }
        }
        // no loop-end sync: next iteration's top sync protects the buffers
    }

    // z reduction
#pragma unroll
    for (int mt = 0; mt < 2; mt++)
#pragma unroll
        for (int hf = 0; hf < 2; hf++) {
            float z = zacc[mt][hf];
            z += __shfl_xor_sync(0xffffffffu, z, 1);
            z += __shfl_xor_sync(0xffffffffu, z, 2);
            if (qid == 0) zbuf[wn * 128 + wm * 32 + mt * 16 + hf * 8 + grp] = z;
        }
    __syncthreads();        // all compute done; K/V smem now dead

    // merge acc1 across wn pairs via smem (reuse K/V region, padded stride)
    float* mrg = (float*)smc;
    if (wn == 1) {
#pragma unroll
        for (int mt = 0; mt < 2; mt++) {
            int r = wm * 32 + mt * 16 + grp;
#pragma unroll
            for (int nt = 0; nt < 8; nt++) {
                int d = nt * 8 + qid * 2;
                *(float2*)&mrg[r * MRGS + d]       = make_float2(acc1[mt][nt][0], acc1[mt][nt][1]);
                *(float2*)&mrg[(r + 8) * MRGS + d] = make_float2(acc1[mt][nt][2], acc1[mt][nt][3]);
            }
        }
    }
    if (tid < 128) sz[tid] = zbuf[tid] + zbuf[128 + tid];
    __syncthreads();

    if (wn == 0) {
        const float inv2049 = 1.0f / 2049.0f;
#pragma unroll
        for (int mt = 0; mt < 2; mt++) {
            int rl = wm * 32 + mt * 16 + grp;
            float iz0 = 1.0f / sz[rl];
            float iz1 = 1.0f / sz[rl + 8];
#pragma unroll
            for (int nt = 0; nt < 8; nt++) {
                int d = nt * 8 + qid * 2;
                float2 m0 = *(float2*)&mrg[rl * MRGS + d];
                float2 m1 = *(float2*)&mrg[(rl + 8) * MRGS + d];
                float a0 = acc1[mt][nt][0] + m0.x;
                float a1 = acc1[mt][nt][1] + m0.y;
                float a2 = acc1[mt][nt][2] + m1.x;
                float a3 = acc1[mt][nt][3] + m1.y;
                float sv0 = sumv[bh * DK + d];
                float sv1 = sumv[bh * DK + d + 1];
                int c = h * DK + d;
                size_t o0 = ((size_t)(b * S_ + q0 + rl)) * D_ + c;
                size_t o1 = ((size_t)(b * S_ + q0 + rl + 8)) * D_ + c;
                *(__half2*)&aout[o0] = __floats2half2_rn((sv0 + a0 * iz0) * inv2049,
                                                         (sv1 + a1 * iz0) * inv2049);
                *(__half2*)&aout[o1] = __floats2half2_rn((sv0 + a2 * iz1) * inv2049,
                                                         (sv1 + a3 * iz1) * inv2049);
            }
        }
    }
}

// ---------------- launch ----------------
extern "C" void kernel_launch(void* const* d_in, const int* in_sizes, int n_in,
                              void* d_out, int out_size) {
    const float* x  = (const float*)d_in[0];
    const float* fc = (const float*)d_in[1];
    const float* fs = (const float*)d_in[2];
    const float* W[4] = {(const float*)d_in[3], (const float*)d_in[4],
                         (const float*)d_in[5], (const float*)d_in[6]};
    float* out = (float*)d_out;

    float *v, *sumvp, *svp;
    __half *xh, *ah, *wt, *qh, *kh, *vth;
    cudaGetSymbolAddress((void**)&v, g_v);
    cudaGetSymbolAddress((void**)&sumvp, g_sumv);
    cudaGetSymbolAddress((void**)&svp, g_svp);
    cudaGetSymbolAddress((void**)&xh, g_xh);
    cudaGetSymbolAddress((void**)&ah, g_ah);
    cudaGetSymbolAddress((void**)&wt, g_wt);
    cudaGetSymbolAddress((void**)&qh, g_qh);
    cudaGetSymbolAddress((void**)&kh, g_kh);
    cudaGetSymbolAddress((void**)&vth, g_vth);

    cudaFuncSetAttribute(gemm_qkv, cudaFuncAttributeMaxDynamicSharedMemorySize, G1SMEM);
    cudaFuncSetAttribute(gemm_f16, cudaFuncAttributeMaxDynamicSharedMemorySize, G1SMEM);
    cudaFuncSetAttribute(attn_fused, cudaFuncAttributeMaxDynamicSharedMemorySize, FASMEM);

    convX<<<(MS_ * D_) / 256, 256>>>(x, xh);
    convWT4<<<dim3(32, 32, 4), 256>>>(W[0], W[1], W[2], W[3], wt);

    gemm_qkv<<<dim3(8, 32, 3), 256, G1SMEM>>>(xh, wt, fc, fs, qh, kh, v);

    vtrans_ps<<<dim3(S_ / 32, DK / 32, BH_), 256>>>(v, vth, svp);
    sumv_final<<<8, 256>>>(svp, sumvp);

    attn_fused<<<dim3(S_ / 128, BH_), 256, FASMEM>>>(qh, kh, vth, sumvp, ah);

    gemm_f16<<<dim3(8, 32), 256, G1SMEM>>>(ah, wt + 3 * (size_t)D_ * D_, out);
}